// round 7
// baseline (speedup 1.0000x reference)
#include <cuda_runtime.h>
#include <cuda_bf16.h>
#include <cstdint>
#include <cstddef>

#define MTOT 8192
#define HDIM 4096
#define IDIM 16384
#define WCNT 67108864ULL
#define EPSF 1e-5f

// ---------------- scratch (device globals; no allocations) ----------------
__device__ __align__(16) signed char g_wq1[(size_t)IDIM * HDIM];  // 64MB
__device__ __align__(16) signed char g_wq2[(size_t)IDIM * HDIM];  // 64MB
__device__ __align__(16) signed char g_xq[(size_t)MTOT * HDIM];   // 32MB
__device__ __align__(16) signed char g_hq[(size_t)MTOT * IDIM];   // 128MB
__device__ __align__(16) float g_h[(size_t)MTOT * IDIM];          // 512MB
__device__ float g_sx[MTOT];
__device__ float g_sh[MTOT];
__device__ unsigned int g_rowmax[MTOT];
__device__ unsigned long long g_wpart[2][2048];
__device__ float g_swf[2];

// ---------------- PTX helpers ----------------
static __device__ __forceinline__ uint32_t smem_u32(const void* p) {
    uint32_t a;
    asm("{ .reg .u64 t; cvta.to.shared.u64 t, %1; cvt.u32.u64 %0, t; }" : "=r"(a) : "l"(p));
    return a;
}
#define CP_ASYNC16(dst, src) \
    asm volatile("cp.async.cg.shared.global [%0], [%1], 16;" :: "r"(dst), "l"(src))
#define CP_COMMIT() asm volatile("cp.async.commit_group;" ::: "memory")
#define CP_WAIT(n)  asm volatile("cp.async.wait_group " #n ";" ::: "memory")
#define BARRIER(id) asm volatile("bar.sync %0, 256;" :: "r"(id) : "memory")

#define LDSM4(r0, r1, r2, r3, addr) \
    asm volatile("ldmatrix.sync.aligned.m8n8.x4.shared.b16 {%0,%1,%2,%3}, [%4];" \
                 : "=r"(r0), "=r"(r1), "=r"(r2), "=r"(r3) : "r"(addr))

#define MMA_S8(d, a, b0, b1) \
    asm volatile("mma.sync.aligned.m16n8k32.row.col.s32.s8.s8.s32 " \
                 "{%0,%1,%2,%3}, {%4,%5,%6,%7}, {%8,%9}, {%0,%1,%2,%3};" \
                 : "+r"((d)[0]), "+r"((d)[1]), "+r"((d)[2]), "+r"((d)[3]) \
                 : "r"((a)[0]), "r"((a)[1]), "r"((a)[2]), "r"((a)[3]), \
                   "r"(b0), "r"(b1))

#define LDS128(r0, r1, r2, r3, addr) \
    asm volatile("ld.shared.v4.u32 {%0,%1,%2,%3},[%4];" \
                 : "=r"(r0), "=r"(r1), "=r"(r2), "=r"(r3) : "r"(addr))

// ---------------- elementwise kernels ----------------
__global__ void k_abssum(const float4* __restrict__ w, int which) {
    unsigned long long acc = 0;
    size_t n4 = WCNT / 4;
    for (size_t i = (size_t)blockIdx.x * blockDim.x + threadIdx.x; i < n4;
         i += (size_t)gridDim.x * blockDim.x) {
        float4 v = w[i];
        acc += (unsigned long long)llrintf(fabsf(v.x) * 1099511627776.f);
        acc += (unsigned long long)llrintf(fabsf(v.y) * 1099511627776.f);
        acc += (unsigned long long)llrintf(fabsf(v.z) * 1099511627776.f);
        acc += (unsigned long long)llrintf(fabsf(v.w) * 1099511627776.f);
    }
    for (int o = 16; o > 0; o >>= 1)
        acc += __shfl_down_sync(0xFFFFFFFFu, acc, o);
    __shared__ unsigned long long s[8];
    if ((threadIdx.x & 31) == 0) s[threadIdx.x >> 5] = acc;
    __syncthreads();
    if (threadIdx.x == 0) {
        unsigned long long t = 0;
        #pragma unroll
        for (int i = 0; i < 8; i++) t += s[i];
        g_wpart[which][blockIdx.x] = t;
    }
}

static __device__ __forceinline__ float reduce_sw(int which) {
    unsigned long long acc = 0;
    #pragma unroll
    for (int i = 0; i < 8; i++)
        acc += g_wpart[which][threadIdx.x * 8 + i];
    for (int o = 16; o > 0; o >>= 1)
        acc += __shfl_down_sync(0xFFFFFFFFu, acc, o);
    __shared__ unsigned long long s[8];
    __shared__ float sws;
    if ((threadIdx.x & 31) == 0) s[threadIdx.x >> 5] = acc;
    __syncthreads();
    if (threadIdx.x == 0) {
        unsigned long long t = 0;
        #pragma unroll
        for (int i = 0; i < 8; i++) t += s[i];
        double mean = (double)t * (1.0 / 1099511627776.0) / 67108864.0;
        sws = (float)fmax(mean, (double)EPSF);
    }
    __syncthreads();
    return sws;
}

template <int WHICH>
__global__ void k_quantw(const float4* __restrict__ w) {
    float sw = reduce_sw(WHICH);
    if (blockIdx.x == 0 && threadIdx.x == 0) g_swf[WHICH] = sw;
    char4* q = (char4*)(WHICH ? g_wq2 : g_wq1);
    size_t n4 = WCNT / 4;
    for (size_t i = (size_t)blockIdx.x * blockDim.x + threadIdx.x; i < n4;
         i += (size_t)gridDim.x * blockDim.x) {
        float4 v = w[i];
        char4 o;
        o.x = (signed char)(int)fminf(fmaxf(rintf(__fdiv_rn(v.x, sw)), -1.f), 1.f);
        o.y = (signed char)(int)fminf(fmaxf(rintf(__fdiv_rn(v.y, sw)), -1.f), 1.f);
        o.z = (signed char)(int)fminf(fmaxf(rintf(__fdiv_rn(v.z, sw)), -1.f), 1.f);
        o.w = (signed char)(int)fminf(fmaxf(rintf(__fdiv_rn(v.w, sw)), -1.f), 1.f);
        q[i] = o;
    }
}

static __device__ __forceinline__ signed char q8(float x, float s) {
    return (signed char)(int)fminf(fmaxf(rintf(__fdiv_rn(x, s)), -128.f), 127.f);
}

__global__ void k_quantx(const float* __restrict__ x) {
    int row = blockIdx.x;
    int t = threadIdx.x;
    if (t == 0) g_rowmax[row] = 0u;
    const float4* xr = (const float4*)(x + (size_t)row * HDIM);
    float4 v[4];
    float m = 0.f;
    #pragma unroll
    for (int i = 0; i < 4; i++) {
        v[i] = xr[t * 4 + i];
        m = fmaxf(m, fmaxf(fmaxf(fabsf(v[i].x), fabsf(v[i].y)),
                           fmaxf(fabsf(v[i].z), fabsf(v[i].w))));
    }
    for (int o = 16; o > 0; o >>= 1)
        m = fmaxf(m, __shfl_xor_sync(0xFFFFFFFFu, m, o));
    __shared__ float sm[8];
    __shared__ float ssx;
    if ((t & 31) == 0) sm[t >> 5] = m;
    __syncthreads();
    if (t == 0) {
        float mm = sm[0];
        #pragma unroll
        for (int i = 1; i < 8; i++) mm = fmaxf(mm, sm[i]);
        float sx = __fdiv_rn(fmaxf(mm, EPSF), 127.f);
        g_sx[row] = sx;
        ssx = sx;
    }
    __syncthreads();
    float sx = ssx;
    char4* out = (char4*)(g_xq + (size_t)row * HDIM);
    #pragma unroll
    for (int i = 0; i < 4; i++) {
        float4 u = v[i];
        char4 o;
        o.x = q8(u.x, sx); o.y = q8(u.y, sx); o.z = q8(u.z, sx); o.w = q8(u.w, sx);
        out[t * 4 + i] = o;
    }
}

__global__ void k_quanth() {
    int row = blockIdx.x;
    float sh = __fdiv_rn(fmaxf(__uint_as_float(g_rowmax[row]), EPSF), 127.f);
    if (threadIdx.x == 0) g_sh[row] = sh;
    const float4* hr = (const float4*)(g_h + (size_t)row * IDIM);
    char4* out = (char4*)(g_hq + (size_t)row * IDIM);
    for (int i = threadIdx.x; i < IDIM / 4; i += blockDim.x) {
        float4 u = hr[i];
        char4 o;
        o.x = q8(u.x, sh); o.y = q8(u.y, sh); o.z = q8(u.z, sh); o.w = q8(u.w, sh);
        out[i] = o;
    }
}

// ====== hybrid GEMM: 512 threads; warps 0-7 = mma (K-chunks [0,T)), warps 8-15 = dp4a ([T,NK))
// D[128x128] tile; dp4a partials combined exactly (s32) in epilogue.
// smem: [0,3S) mma stages | [3S,6S) dp4a stages | [6S, +128*132*4) s32 partial tile
template <int MODE>
__global__ __launch_bounds__(512, 1) void k_gemm(float* __restrict__ outp) {
    constexpr int K = MODE ? IDIM : HDIM;
    constexpr int N = MODE ? HDIM : IDIM;
    constexpr int NK = K / 64;
    constexpr int T = MODE ? 152 : 38;      // tensor-group K-chunks
    constexpr int ND = NK - T;              // dp4a-group K-chunks
    constexpr int STAGE = 20480;            // (128 A + 128 B rows) * 80B
    const signed char* Ag = MODE ? g_hq : g_xq;
    const signed char* Bg = MODE ? g_wq2 : g_wq1;
    float* Out = MODE ? outp : g_h;
    const float* srow = MODE ? g_sh : g_sx;

    extern __shared__ __align__(128) char smem[];
    uint32_t smbase = smem_u32(smem);
    int* Ssm = (int*)(smem + 6 * STAGE);    // 128 x 132 s32

    int tid = threadIdx.x;
    int gt = tid & 255;
    bool is_mma = tid < 256;

    int mt = MODE ? blockIdx.y : blockIdx.x;
    int nt = MODE ? blockIdx.x : blockIdx.y;
    int mb = mt * 128, nb = nt * 128;

    uint32_t gbase = smbase + (is_mma ? 0u : (uint32_t)(3 * STAGE));
    auto load_stage = [&](int s, int kc) {
        uint32_t base = gbase + s * STAGE;
        const signed char* ag = Ag + (size_t)mb * K + (size_t)kc * 64;
        const signed char* bg = Bg + (size_t)nb * K + (size_t)kc * 64;
        #pragma unroll
        for (int i = 0; i < 2; i++) {
            int c = gt + i * 256;
            int r = c >> 2, cc = c & 3;
            CP_ASYNC16(base + r * 80 + cc * 16, ag + (size_t)r * K + cc * 16);
        }
        #pragma unroll
        for (int i = 0; i < 2; i++) {
            int c = gt + i * 256;
            int r = c >> 2, cc = c & 3;
            CP_ASYNC16(base + 10240 + r * 80 + cc * 16, bg + (size_t)r * K + cc * 16);
        }
        CP_COMMIT();
    };

    int acc[4][4][4];  // mma accumulators (only used by mma group)

    if (is_mma) {
        // ---------------- tensor group: K-chunks [0, T) ----------------
        int wid = gt >> 5, lane = gt & 31;
        int wm = wid & 1, wn = wid >> 1;
        int rq = lane & 7, q = lane >> 3;
        #pragma unroll
        for (int i = 0; i < 4; i++)
            #pragma unroll
            for (int j = 0; j < 4; j++)
                #pragma unroll
                for (int c = 0; c < 4; c++) acc[i][j][c] = 0;

        int lrow = rq + (q & 1) * 8;
        int lcol = (q >> 1) * 16;
        int aoff[4], boff[2];
        #pragma unroll
        for (int m = 0; m < 4; m++) aoff[m] = (wm * 64 + m * 16 + lrow) * 80 + lcol;
        #pragma unroll
        for (int bt = 0; bt < 2; bt++) boff[bt] = 10240 + (wn * 32 + bt * 16 + lrow) * 80 + lcol;

        load_stage(0, 0);
        load_stage(1, 1);
        for (int k = 0; k < T; k++) {
            if (k < T - 1) { CP_WAIT(1); } else { CP_WAIT(0); }
            BARRIER(1);   // all mma warps done with stage being overwritten below
            if (k + 2 < T) load_stage((k + 2) % 3, k + 2);

            uint32_t sA = gbase + (k % 3) * STAGE;
            #pragma unroll
            for (int ks = 0; ks < 2; ks++) {
                uint32_t af[4][4], bf[2][4];
                #pragma unroll
                for (int m = 0; m < 4; m++)
                    LDSM4(af[m][0], af[m][1], af[m][2], af[m][3], sA + aoff[m] + ks * 32);
                #pragma unroll
                for (int bt = 0; bt < 2; bt++)
                    LDSM4(bf[bt][0], bf[bt][1], bf[bt][2], bf[bt][3], sA + boff[bt] + ks * 32);
                #pragma unroll
                for (int m = 0; m < 4; m++)
                    #pragma unroll
                    for (int bt = 0; bt < 2; bt++) {
                        MMA_S8(acc[m][bt * 2 + 0], af[m], bf[bt][0], bf[bt][2]);
                        MMA_S8(acc[m][bt * 2 + 1], af[m], bf[bt][1], bf[bt][3]);
                    }
            }
        }
    } else {
        // ---------------- dp4a group: K-chunks [T, NK) ----------------
        int r8 = (gt >> 4) * 8;   // row block base (16 blocks of 8 rows)
        int c0 = gt & 15;         // col base; cols = c0 + 16*j2
        int dacc[8][8];
        #pragma unroll
        for (int i = 0; i < 8; i++)
            #pragma unroll
            for (int j = 0; j < 8; j++) dacc[i][j] = 0;

        load_stage(0, T);
        load_stage(1, T + 1);
        for (int k = 0; k < ND; k++) {
            if (k < ND - 1) { CP_WAIT(1); } else { CP_WAIT(0); }
            BARRIER(2);
            if (k + 2 < ND) load_stage((k + 2) % 3, T + k + 2);

            uint32_t sA = gbase + (k % 3) * STAGE;
            uint32_t sB = sA + 10240;
            #pragma unroll
            for (int cp = 0; cp < 4; cp++) {   // 4 x 16B phases (LDS128)
                uint32_t b[8][4];
                #pragma unroll
                for (int j2 = 0; j2 < 8; j2++)
                    LDS128(b[j2][0], b[j2][1], b[j2][2], b[j2][3],
                           sB + (c0 + 16 * j2) * 80 + cp * 16);
                #pragma unroll
                for (int i = 0; i < 8; i++) {
                    uint32_t a0, a1, a2, a3;
                    LDS128(a0, a1, a2, a3, sA + (r8 + i) * 80 + cp * 16);
                    #pragma unroll
                    for (int j2 = 0; j2 < 8; j2++) {
                        dacc[i][j2] = __dp4a((int)a0, (int)b[j2][0], dacc[i][j2]);
                        dacc[i][j2] = __dp4a((int)a1, (int)b[j2][1], dacc[i][j2]);
                        dacc[i][j2] = __dp4a((int)a2, (int)b[j2][2], dacc[i][j2]);
                        dacc[i][j2] = __dp4a((int)a3, (int)b[j2][3], dacc[i][j2]);
                    }
                }
            }
        }
        // write s32 partials to smem tile (stride 132 words)
        #pragma unroll
        for (int i = 0; i < 8; i++)
            #pragma unroll
            for (int j2 = 0; j2 < 8; j2++)
                Ssm[(r8 + i) * 132 + c0 + 16 * j2] = dacc[i][j2];
    }

    __syncthreads();   // join: dp4a partials visible

    if (is_mma) {
        // ---------------- epilogue (mma warps): combine + dequant (+gelu/rowmax) ----
        int wid = gt >> 5, lane = gt & 31;
        int wm = wid & 1, wn = wid >> 1;
        int g = lane >> 2, tig = lane & 3;
        float sw = g_swf[MODE];
        #pragma unroll
        for (int m = 0; m < 4; m++) {
            int rL0 = wm * 64 + m * 16 + g;
            int row0 = mb + rL0;
            int row1 = row0 + 8;
            float s0 = srow[row0] * sw;
            float s1 = srow[row1] * sw;
            float mx0 = 0.f, mx1 = 0.f;
            #pragma unroll
            for (int j = 0; j < 4; j++) {
                int colL = wn * 32 + j * 8 + tig * 2;
                int2 d0 = *(const int2*)(Ssm + rL0 * 132 + colL);
                int2 d1 = *(const int2*)(Ssm + (rL0 + 8) * 132 + colL);
                float v00 = (float)(acc[m][j][0] + d0.x) * s0;
                float v01 = (float)(acc[m][j][1] + d0.y) * s0;
                float v10 = (float)(acc[m][j][2] + d1.x) * s1;
                float v11 = (float)(acc[m][j][3] + d1.y) * s1;
                if (MODE == 0) {
                    v00 = 0.5f * v00 * (1.f + erff(v00 * 0.70710678118654752f));
                    v01 = 0.5f * v01 * (1.f + erff(v01 * 0.70710678118654752f));
                    v10 = 0.5f * v10 * (1.f + erff(v10 * 0.70710678118654752f));
                    v11 = 0.5f * v11 * (1.f + erff(v11 * 0.70710678118654752f));
                    mx0 = fmaxf(mx0, fmaxf(fabsf(v00), fabsf(v01)));
                    mx1 = fmaxf(mx1, fmaxf(fabsf(v10), fabsf(v11)));
                }
                *(float2*)(Out + (size_t)row0 * N + nb + colL) = make_float2(v00, v01);
                *(float2*)(Out + (size_t)row1 * N + nb + colL) = make_float2(v10, v11);
            }
            if (MODE == 0) {
                #pragma unroll
                for (int o = 1; o < 4; o <<= 1) {
                    mx0 = fmaxf(mx0, __shfl_xor_sync(0xFFFFFFFFu, mx0, o));
                    mx1 = fmaxf(mx1, __shfl_xor_sync(0xFFFFFFFFu, mx1, o));
                }
                if (tig == 0) {
                    atomicMax(&g_rowmax[row0], __float_as_uint(mx0));
                    atomicMax(&g_rowmax[row1], __float_as_uint(mx1));
                }
            }
        }
    }
}

// ---------------- launch ----------------
extern "C" void kernel_launch(void* const* d_in, const int* in_sizes, int n_in,
                              void* d_out, int out_size) {
    const float* x  = (const float*)d_in[0];
    const float* W1 = (const float*)d_in[1];
    const float* W2 = (const float*)d_in[2];
    float* out = (float*)d_out;

    const int SMEM = 6 * 20480 + 128 * 132 * 4;   // 190464
    cudaFuncSetAttribute(k_gemm<0>, cudaFuncAttributeMaxDynamicSharedMemorySize, SMEM);
    cudaFuncSetAttribute(k_gemm<1>, cudaFuncAttributeMaxDynamicSharedMemorySize, SMEM);

    k_abssum<<<2048, 256>>>((const float4*)W1, 0);   // 0
    k_quantw<0><<<4096, 256>>>((const float4*)W1);   // 1
    k_quantx<<<MTOT, 256>>>(x);                      // 2 (also zeroes rowmax)
    k_gemm<0><<<dim3(64, 128), 512, SMEM>>>(out);    // 3  <- ncu capture slot
    k_quanth<<<MTOT, 256>>>();                       // 4
    k_abssum<<<2048, 256>>>((const float4*)W2, 1);   // 5
    k_quantw<1><<<4096, 256>>>((const float4*)W2);   // 6
    k_gemm<1><<<dim3(32, 64), 512, SMEM>>>(out);     // 7
}

// round 8
// speedup vs baseline: 1.5596x; 1.5596x over previous
#include <cuda_runtime.h>
#include <cuda_bf16.h>
#include <cstdint>
#include <cstddef>

#define MTOT 8192
#define HDIM 4096
#define IDIM 16384
#define WCNT 67108864ULL
#define EPSF 1e-5f

// ---------------- scratch (device globals; no allocations) ----------------
__device__ __align__(16) signed char g_wq1[(size_t)IDIM * HDIM];  // 64MB
__device__ __align__(16) signed char g_wq2[(size_t)IDIM * HDIM];  // 64MB
__device__ __align__(16) signed char g_xq[(size_t)MTOT * HDIM];   // 32MB
__device__ __align__(16) signed char g_hq[(size_t)MTOT * IDIM];   // 128MB
__device__ __align__(16) float g_h[(size_t)MTOT * IDIM];          // 512MB
__device__ float g_sx[MTOT];
__device__ float g_sh[MTOT];
__device__ unsigned int g_rowmax[MTOT];
__device__ unsigned long long g_wpart[2][2048];
__device__ float g_swf[2];

// ---------------- PTX helpers ----------------
static __device__ __forceinline__ uint32_t smem_u32(const void* p) {
    uint32_t a;
    asm("{ .reg .u64 t; cvta.to.shared.u64 t, %1; cvt.u32.u64 %0, t; }" : "=r"(a) : "l"(p));
    return a;
}
#define CP_ASYNC16(dst, src) \
    asm volatile("cp.async.cg.shared.global [%0], [%1], 16;" :: "r"(dst), "l"(src))
#define CP_COMMIT() asm volatile("cp.async.commit_group;" ::: "memory")
#define CP_WAIT(n)  asm volatile("cp.async.wait_group " #n ";" ::: "memory")
#define BARRIER(id) asm volatile("bar.sync %0, 256;" :: "r"(id) : "memory")

#define LDSM4(r0, r1, r2, r3, addr) \
    asm volatile("ldmatrix.sync.aligned.m8n8.x4.shared.b16 {%0,%1,%2,%3}, [%4];" \
                 : "=r"(r0), "=r"(r1), "=r"(r2), "=r"(r3) : "r"(addr))

#define MMA_S8(d, a, b0, b1) \
    asm volatile("mma.sync.aligned.m16n8k32.row.col.s32.s8.s8.s32 " \
                 "{%0,%1,%2,%3}, {%4,%5,%6,%7}, {%8,%9}, {%0,%1,%2,%3};" \
                 : "+r"((d)[0]), "+r"((d)[1]), "+r"((d)[2]), "+r"((d)[3]) \
                 : "r"((a)[0]), "r"((a)[1]), "r"((a)[2]), "r"((a)[3]), \
                   "r"(b0), "r"(b1))

#define LDS64(r0, r1, addr) \
    asm volatile("ld.shared.v2.u32 {%0,%1},[%2];" : "=r"(r0), "=r"(r1) : "r"(addr))

// ---------------- elementwise kernels ----------------
__global__ void k_abssum(const float4* __restrict__ w, int which) {
    unsigned long long acc = 0;
    size_t n4 = WCNT / 4;
    for (size_t i = (size_t)blockIdx.x * blockDim.x + threadIdx.x; i < n4;
         i += (size_t)gridDim.x * blockDim.x) {
        float4 v = w[i];
        acc += (unsigned long long)llrintf(fabsf(v.x) * 1099511627776.f);
        acc += (unsigned long long)llrintf(fabsf(v.y) * 1099511627776.f);
        acc += (unsigned long long)llrintf(fabsf(v.z) * 1099511627776.f);
        acc += (unsigned long long)llrintf(fabsf(v.w) * 1099511627776.f);
    }
    for (int o = 16; o > 0; o >>= 1)
        acc += __shfl_down_sync(0xFFFFFFFFu, acc, o);
    __shared__ unsigned long long s[8];
    if ((threadIdx.x & 31) == 0) s[threadIdx.x >> 5] = acc;
    __syncthreads();
    if (threadIdx.x == 0) {
        unsigned long long t = 0;
        #pragma unroll
        for (int i = 0; i < 8; i++) t += s[i];
        g_wpart[which][blockIdx.x] = t;
    }
}

static __device__ __forceinline__ float reduce_sw(int which) {
    unsigned long long acc = 0;
    #pragma unroll
    for (int i = 0; i < 8; i++)
        acc += g_wpart[which][threadIdx.x * 8 + i];
    for (int o = 16; o > 0; o >>= 1)
        acc += __shfl_down_sync(0xFFFFFFFFu, acc, o);
    __shared__ unsigned long long s[8];
    __shared__ float sws;
    if ((threadIdx.x & 31) == 0) s[threadIdx.x >> 5] = acc;
    __syncthreads();
    if (threadIdx.x == 0) {
        unsigned long long t = 0;
        #pragma unroll
        for (int i = 0; i < 8; i++) t += s[i];
        double mean = (double)t * (1.0 / 1099511627776.0) / 67108864.0;
        sws = (float)fmax(mean, (double)EPSF);
    }
    __syncthreads();
    return sws;
}

template <int WHICH>
__global__ void k_quantw(const float4* __restrict__ w) {
    float sw = reduce_sw(WHICH);
    if (blockIdx.x == 0 && threadIdx.x == 0) g_swf[WHICH] = sw;
    char4* q = (char4*)(WHICH ? g_wq2 : g_wq1);
    size_t n4 = WCNT / 4;
    for (size_t i = (size_t)blockIdx.x * blockDim.x + threadIdx.x; i < n4;
         i += (size_t)gridDim.x * blockDim.x) {
        float4 v = w[i];
        char4 o;
        o.x = (signed char)(int)fminf(fmaxf(rintf(__fdiv_rn(v.x, sw)), -1.f), 1.f);
        o.y = (signed char)(int)fminf(fmaxf(rintf(__fdiv_rn(v.y, sw)), -1.f), 1.f);
        o.z = (signed char)(int)fminf(fmaxf(rintf(__fdiv_rn(v.z, sw)), -1.f), 1.f);
        o.w = (signed char)(int)fminf(fmaxf(rintf(__fdiv_rn(v.w, sw)), -1.f), 1.f);
        q[i] = o;
    }
}

static __device__ __forceinline__ signed char q8(float x, float s) {
    return (signed char)(int)fminf(fmaxf(rintf(__fdiv_rn(x, s)), -128.f), 127.f);
}

__global__ void k_quantx(const float* __restrict__ x) {
    int row = blockIdx.x;
    int t = threadIdx.x;
    if (t == 0) g_rowmax[row] = 0u;
    const float4* xr = (const float4*)(x + (size_t)row * HDIM);
    float4 v[4];
    float m = 0.f;
    #pragma unroll
    for (int i = 0; i < 4; i++) {
        v[i] = xr[t * 4 + i];
        m = fmaxf(m, fmaxf(fmaxf(fabsf(v[i].x), fabsf(v[i].y)),
                           fmaxf(fabsf(v[i].z), fabsf(v[i].w))));
    }
    for (int o = 16; o > 0; o >>= 1)
        m = fmaxf(m, __shfl_xor_sync(0xFFFFFFFFu, m, o));
    __shared__ float sm[8];
    __shared__ float ssx;
    if ((t & 31) == 0) sm[t >> 5] = m;
    __syncthreads();
    if (t == 0) {
        float mm = sm[0];
        #pragma unroll
        for (int i = 1; i < 8; i++) mm = fmaxf(mm, sm[i]);
        float sx = __fdiv_rn(fmaxf(mm, EPSF), 127.f);
        g_sx[row] = sx;
        ssx = sx;
    }
    __syncthreads();
    float sx = ssx;
    char4* out = (char4*)(g_xq + (size_t)row * HDIM);
    #pragma unroll
    for (int i = 0; i < 4; i++) {
        float4 u = v[i];
        char4 o;
        o.x = q8(u.x, sx); o.y = q8(u.y, sx); o.z = q8(u.z, sx); o.w = q8(u.w, sx);
        out[t * 4 + i] = o;
    }
}

__global__ void k_quanth() {
    int row = blockIdx.x;
    float sh = __fdiv_rn(fmaxf(__uint_as_float(g_rowmax[row]), EPSF), 127.f);
    if (threadIdx.x == 0) g_sh[row] = sh;
    const float4* hr = (const float4*)(g_h + (size_t)row * IDIM);
    char4* out = (char4*)(g_hq + (size_t)row * IDIM);
    for (int i = threadIdx.x; i < IDIM / 4; i += blockDim.x) {
        float4 u = hr[i];
        char4 o;
        o.x = q8(u.x, sh); o.y = q8(u.y, sh); o.z = q8(u.z, sh); o.w = q8(u.w, sh);
        out[i] = o;
    }
}

// ====== hybrid GEMM: 512 threads; warps 0-7 = mma (K-chunks [0,T)), warps 8-15 = dp4a ([T,NK))
// D[128x128] tile; dp4a partials combined exactly (s32) in epilogue.
// smem: [0,3S) mma stages | [3S,6S) dp4a stages | [6S, +128*132*4) s32 partial tile
template <int MODE>
__global__ __launch_bounds__(512, 1) void k_gemm(float* __restrict__ outp) {
    constexpr int K = MODE ? IDIM : HDIM;
    constexpr int N = MODE ? HDIM : IDIM;
    constexpr int NK = K / 64;
    constexpr int T = MODE ? 160 : 40;      // tensor-group K-chunks (balanced at cd/ct=1.64)
    constexpr int ND = NK - T;              // dp4a-group K-chunks
    constexpr int STAGE = 20480;            // (128 A + 128 B rows) * 80B
    const signed char* Ag = MODE ? g_hq : g_xq;
    const signed char* Bg = MODE ? g_wq2 : g_wq1;
    float* Out = MODE ? outp : g_h;
    const float* srow = MODE ? g_sh : g_sx;

    extern __shared__ __align__(128) char smem[];
    uint32_t smbase = smem_u32(smem);
    int* Ssm = (int*)(smem + 6 * STAGE);    // 128 x 132 s32

    int tid = threadIdx.x;
    int gt = tid & 255;
    bool is_mma = tid < 256;

    int mt = MODE ? blockIdx.y : blockIdx.x;
    int nt = MODE ? blockIdx.x : blockIdx.y;
    int mb = mt * 128, nb = nt * 128;

    uint32_t gbase = smbase + (is_mma ? 0u : (uint32_t)(3 * STAGE));
    auto load_stage = [&](int s, int kc) {
        uint32_t base = gbase + s * STAGE;
        const signed char* ag = Ag + (size_t)mb * K + (size_t)kc * 64;
        const signed char* bg = Bg + (size_t)nb * K + (size_t)kc * 64;
        #pragma unroll
        for (int i = 0; i < 2; i++) {
            int c = gt + i * 256;
            int r = c >> 2, cc = c & 3;
            CP_ASYNC16(base + r * 80 + cc * 16, ag + (size_t)r * K + cc * 16);
        }
        #pragma unroll
        for (int i = 0; i < 2; i++) {
            int c = gt + i * 256;
            int r = c >> 2, cc = c & 3;
            CP_ASYNC16(base + 10240 + r * 80 + cc * 16, bg + (size_t)r * K + cc * 16);
        }
        CP_COMMIT();
    };

    int acc[4][4][4];  // mma accumulators (only used by mma group)

    if (is_mma) {
        // ---------------- tensor group: K-chunks [0, T) ----------------
        int wid = gt >> 5, lane = gt & 31;
        int wm = wid & 1, wn = wid >> 1;
        int rq = lane & 7, q = lane >> 3;
        #pragma unroll
        for (int i = 0; i < 4; i++)
            #pragma unroll
            for (int j = 0; j < 4; j++)
                #pragma unroll
                for (int c = 0; c < 4; c++) acc[i][j][c] = 0;

        int lrow = rq + (q & 1) * 8;
        int lcol = (q >> 1) * 16;
        int aoff[4], boff[2];
        #pragma unroll
        for (int m = 0; m < 4; m++) aoff[m] = (wm * 64 + m * 16 + lrow) * 80 + lcol;
        #pragma unroll
        for (int bt = 0; bt < 2; bt++) boff[bt] = 10240 + (wn * 32 + bt * 16 + lrow) * 80 + lcol;

        load_stage(0, 0);
        load_stage(1, 1);
        for (int k = 0; k < T; k++) {
            if (k < T - 1) { CP_WAIT(1); } else { CP_WAIT(0); }
            BARRIER(1);
            if (k + 2 < T) load_stage((k + 2) % 3, k + 2);

            uint32_t sA = gbase + (k % 3) * STAGE;
            #pragma unroll
            for (int ks = 0; ks < 2; ks++) {
                uint32_t af[4][4], bf[2][4];
                #pragma unroll
                for (int m = 0; m < 4; m++)
                    LDSM4(af[m][0], af[m][1], af[m][2], af[m][3], sA + aoff[m] + ks * 32);
                #pragma unroll
                for (int bt = 0; bt < 2; bt++)
                    LDSM4(bf[bt][0], bf[bt][1], bf[bt][2], bf[bt][3], sA + boff[bt] + ks * 32);
                #pragma unroll
                for (int m = 0; m < 4; m++)
                    #pragma unroll
                    for (int bt = 0; bt < 2; bt++) {
                        MMA_S8(acc[m][bt * 2 + 0], af[m], bf[bt][0], bf[bt][2]);
                        MMA_S8(acc[m][bt * 2 + 1], af[m], bf[bt][1], bf[bt][3]);
                    }
            }
            BARRIER(1);
        }
    } else {
        // ---------------- dp4a group: K-chunks [T, NK) ----------------
        int r8 = (gt >> 4) * 8;   // row block base (16 blocks of 8 rows)
        int c0 = gt & 15;         // col base; cols = c0 + 16*j2
        int dacc[8][8];
        #pragma unroll
        for (int i = 0; i < 8; i++)
            #pragma unroll
            for (int j = 0; j < 8; j++) dacc[i][j] = 0;

        load_stage(0, T);
        load_stage(1, T + 1);
        for (int k = 0; k < ND; k++) {
            if (k < ND - 1) { CP_WAIT(1); } else { CP_WAIT(0); }
            BARRIER(2);
            if (k + 2 < ND) load_stage((k + 2) % 3, T + k + 2);

            uint32_t sA = gbase + (k % 3) * STAGE;
            uint32_t sB = sA + 10240;
            #pragma unroll
            for (int cp = 0; cp < 8; cp++) {
                uint32_t b0[8], b1[8];
                #pragma unroll
                for (int j2 = 0; j2 < 8; j2++)
                    LDS64(b0[j2], b1[j2], sB + (c0 + 16 * j2) * 80 + cp * 8);
                #pragma unroll
                for (int i = 0; i < 8; i++) {
                    uint32_t a0, a1;
                    LDS64(a0, a1, sA + (r8 + i) * 80 + cp * 8);
                    #pragma unroll
                    for (int j2 = 0; j2 < 8; j2++) {
                        dacc[i][j2] = __dp4a((int)a0, (int)b0[j2], dacc[i][j2]);
                        dacc[i][j2] = __dp4a((int)a1, (int)b1[j2], dacc[i][j2]);
                    }
                }
            }
            BARRIER(2);
        }
        // write s32 partials to smem tile (stride 132 words)
        #pragma unroll
        for (int i = 0; i < 8; i++)
            #pragma unroll
            for (int j2 = 0; j2 < 8; j2++)
                Ssm[(r8 + i) * 132 + c0 + 16 * j2] = dacc[i][j2];
    }

    __syncthreads();   // join: dp4a partials visible

    if (is_mma) {
        // ---------------- epilogue (mma warps): combine + dequant (+gelu/rowmax) ----
        int wid = gt >> 5, lane = gt & 31;
        int wm = wid & 1, wn = wid >> 1;
        int g = lane >> 2, tig = lane & 3;
        float sw = g_swf[MODE];
        #pragma unroll
        for (int m = 0; m < 4; m++) {
            int rL0 = wm * 64 + m * 16 + g;
            int row0 = mb + rL0;
            int row1 = row0 + 8;
            float s0 = srow[row0] * sw;
            float s1 = srow[row1] * sw;
            float mx0 = 0.f, mx1 = 0.f;
            #pragma unroll
            for (int j = 0; j < 4; j++) {
                int colL = wn * 32 + j * 8 + tig * 2;
                int2 d0 = *(const int2*)(Ssm + rL0 * 132 + colL);
                int2 d1 = *(const int2*)(Ssm + (rL0 + 8) * 132 + colL);
                float v00 = (float)(acc[m][j][0] + d0.x) * s0;
                float v01 = (float)(acc[m][j][1] + d0.y) * s0;
                float v10 = (float)(acc[m][j][2] + d1.x) * s1;
                float v11 = (float)(acc[m][j][3] + d1.y) * s1;
                if (MODE == 0) {
                    v00 = 0.5f * v00 * (1.f + erff(v00 * 0.70710678118654752f));
                    v01 = 0.5f * v01 * (1.f + erff(v01 * 0.70710678118654752f));
                    v10 = 0.5f * v10 * (1.f + erff(v10 * 0.70710678118654752f));
                    v11 = 0.5f * v11 * (1.f + erff(v11 * 0.70710678118654752f));
                    mx0 = fmaxf(mx0, fmaxf(fabsf(v00), fabsf(v01)));
                    mx1 = fmaxf(mx1, fmaxf(fabsf(v10), fabsf(v11)));
                }
                *(float2*)(Out + (size_t)row0 * N + nb + colL) = make_float2(v00, v01);
                *(float2*)(Out + (size_t)row1 * N + nb + colL) = make_float2(v10, v11);
            }
            if (MODE == 0) {
                #pragma unroll
                for (int o = 1; o < 4; o <<= 1) {
                    mx0 = fmaxf(mx0, __shfl_xor_sync(0xFFFFFFFFu, mx0, o));
                    mx1 = fmaxf(mx1, __shfl_xor_sync(0xFFFFFFFFu, mx1, o));
                }
                if (tig == 0) {
                    atomicMax(&g_rowmax[row0], __float_as_uint(mx0));
                    atomicMax(&g_rowmax[row1], __float_as_uint(mx1));
                }
            }
        }
    }
}

// ---------------- launch ----------------
extern "C" void kernel_launch(void* const* d_in, const int* in_sizes, int n_in,
                              void* d_out, int out_size) {
    const float* x  = (const float*)d_in[0];
    const float* W1 = (const float*)d_in[1];
    const float* W2 = (const float*)d_in[2];
    float* out = (float*)d_out;

    const int SMEM = 6 * 20480 + 128 * 132 * 4;   // 190464
    cudaFuncSetAttribute(k_gemm<0>, cudaFuncAttributeMaxDynamicSharedMemorySize, SMEM);
    cudaFuncSetAttribute(k_gemm<1>, cudaFuncAttributeMaxDynamicSharedMemorySize, SMEM);

    k_abssum<<<2048, 256>>>((const float4*)W1, 0);   // 0
    k_quantw<0><<<4096, 256>>>((const float4*)W1);   // 1
    k_quantx<<<MTOT, 256>>>(x);                      // 2 (also zeroes rowmax)
    k_gemm<0><<<dim3(64, 128), 512, SMEM>>>(out);    // 3  <- ncu capture slot
    k_quanth<<<MTOT, 256>>>();                       // 4
    k_abssum<<<2048, 256>>>((const float4*)W2, 1);   // 5
    k_quantw<1><<<4096, 256>>>((const float4*)W2);   // 6
    k_gemm<1><<<dim3(32, 64), 512, SMEM>>>(out);     // 7
}

// round 10
// speedup vs baseline: 1.7598x; 1.1284x over previous
#include <cuda_runtime.h>
#include <cuda_bf16.h>
#include <cstdint>
#include <cstddef>

#define MTOT 8192
#define HDIM 4096
#define IDIM 16384
#define WCNT 67108864ULL
#define EPSF 1e-5f

// ---------------- scratch (device globals; no allocations) ----------------
__device__ __align__(16) signed char g_wq1[(size_t)IDIM * HDIM];  // 64MB
__device__ __align__(16) signed char g_wq2[(size_t)IDIM * HDIM];  // 64MB
__device__ __align__(16) signed char g_xq[(size_t)MTOT * HDIM];   // 32MB
__device__ __align__(16) signed char g_hq[(size_t)MTOT * IDIM];   // 128MB
__device__ __align__(16) float g_h[(size_t)MTOT * IDIM];          // 512MB
__device__ float g_sx[MTOT];
__device__ float g_sh[MTOT];
__device__ unsigned int g_rowmax[MTOT];
__device__ unsigned long long g_wpart[2][2048];
__device__ float g_swf[2];

// ---------------- PTX helpers ----------------
static __device__ __forceinline__ uint32_t smem_u32(const void* p) {
    uint32_t a;
    asm("{ .reg .u64 t; cvta.to.shared.u64 t, %1; cvt.u32.u64 %0, t; }" : "=r"(a) : "l"(p));
    return a;
}
#define CP_ASYNC16(dst, src) \
    asm volatile("cp.async.cg.shared.global [%0], [%1], 16;" :: "r"(dst), "l"(src))
#define CP_COMMIT() asm volatile("cp.async.commit_group;" ::: "memory")
#define CP_WAIT(n)  asm volatile("cp.async.wait_group " #n ";" ::: "memory")
#define BARRIER(id) asm volatile("bar.sync %0, 128;" :: "r"(id) : "memory")

#define LDSM4(r0, r1, r2, r3, addr) \
    asm volatile("ldmatrix.sync.aligned.m8n8.x4.shared.b16 {%0,%1,%2,%3}, [%4];" \
                 : "=r"(r0), "=r"(r1), "=r"(r2), "=r"(r3) : "r"(addr))

#define MMA_S8(d, a, b0, b1) \
    asm volatile("mma.sync.aligned.m16n8k32.row.col.s32.s8.s8.s32 " \
                 "{%0,%1,%2,%3}, {%4,%5,%6,%7}, {%8,%9}, {%0,%1,%2,%3};" \
                 : "+r"((d)[0]), "+r"((d)[1]), "+r"((d)[2]), "+r"((d)[3]) \
                 : "r"((a)[0]), "r"((a)[1]), "r"((a)[2]), "r"((a)[3]), \
                   "r"(b0), "r"(b1))

#define LDS64(r0, r1, addr) \
    asm volatile("ld.shared.v2.u32 {%0,%1},[%2];" : "=r"(r0), "=r"(r1) : "r"(addr))

// ---------------- elementwise kernels ----------------
__global__ void k_abssum(const float4* __restrict__ w, int which) {
    unsigned long long acc = 0;
    size_t n4 = WCNT / 4;
    for (size_t i = (size_t)blockIdx.x * blockDim.x + threadIdx.x; i < n4;
         i += (size_t)gridDim.x * blockDim.x) {
        float4 v = w[i];
        acc += (unsigned long long)llrintf(fabsf(v.x) * 1099511627776.f);
        acc += (unsigned long long)llrintf(fabsf(v.y) * 1099511627776.f);
        acc += (unsigned long long)llrintf(fabsf(v.z) * 1099511627776.f);
        acc += (unsigned long long)llrintf(fabsf(v.w) * 1099511627776.f);
    }
    for (int o = 16; o > 0; o >>= 1)
        acc += __shfl_down_sync(0xFFFFFFFFu, acc, o);
    __shared__ unsigned long long s[8];
    if ((threadIdx.x & 31) == 0) s[threadIdx.x >> 5] = acc;
    __syncthreads();
    if (threadIdx.x == 0) {
        unsigned long long t = 0;
        #pragma unroll
        for (int i = 0; i < 8; i++) t += s[i];
        g_wpart[which][blockIdx.x] = t;
    }
}

static __device__ __forceinline__ float reduce_sw(int which) {
    unsigned long long acc = 0;
    #pragma unroll
    for (int i = 0; i < 8; i++)
        acc += g_wpart[which][threadIdx.x * 8 + i];
    for (int o = 16; o > 0; o >>= 1)
        acc += __shfl_down_sync(0xFFFFFFFFu, acc, o);
    __shared__ unsigned long long s[8];
    __shared__ float sws;
    if ((threadIdx.x & 31) == 0) s[threadIdx.x >> 5] = acc;
    __syncthreads();
    if (threadIdx.x == 0) {
        unsigned long long t = 0;
        #pragma unroll
        for (int i = 0; i < 8; i++) t += s[i];
        double mean = (double)t * (1.0 / 1099511627776.0) / 67108864.0;
        sws = (float)fmax(mean, (double)EPSF);
    }
    __syncthreads();
    return sws;
}

template <int WHICH>
__global__ void k_quantw(const float4* __restrict__ w) {
    float sw = reduce_sw(WHICH);
    if (blockIdx.x == 0 && threadIdx.x == 0) g_swf[WHICH] = sw;
    char4* q = (char4*)(WHICH ? g_wq2 : g_wq1);
    size_t n4 = WCNT / 4;
    for (size_t i = (size_t)blockIdx.x * blockDim.x + threadIdx.x; i < n4;
         i += (size_t)gridDim.x * blockDim.x) {
        float4 v = w[i];
        char4 o;
        o.x = (signed char)(int)fminf(fmaxf(rintf(__fdiv_rn(v.x, sw)), -1.f), 1.f);
        o.y = (signed char)(int)fminf(fmaxf(rintf(__fdiv_rn(v.y, sw)), -1.f), 1.f);
        o.z = (signed char)(int)fminf(fmaxf(rintf(__fdiv_rn(v.z, sw)), -1.f), 1.f);
        o.w = (signed char)(int)fminf(fmaxf(rintf(__fdiv_rn(v.w, sw)), -1.f), 1.f);
        q[i] = o;
    }
}

static __device__ __forceinline__ signed char q8(float x, float s) {
    return (signed char)(int)fminf(fmaxf(rintf(__fdiv_rn(x, s)), -128.f), 127.f);
}

__global__ void k_quantx(const float* __restrict__ x) {
    int row = blockIdx.x;
    int t = threadIdx.x;
    if (t == 0) g_rowmax[row] = 0u;
    const float4* xr = (const float4*)(x + (size_t)row * HDIM);
    float4 v[4];
    float m = 0.f;
    #pragma unroll
    for (int i = 0; i < 4; i++) {
        v[i] = xr[t * 4 + i];
        m = fmaxf(m, fmaxf(fmaxf(fabsf(v[i].x), fabsf(v[i].y)),
                           fmaxf(fabsf(v[i].z), fabsf(v[i].w))));
    }
    for (int o = 16; o > 0; o >>= 1)
        m = fmaxf(m, __shfl_xor_sync(0xFFFFFFFFu, m, o));
    __shared__ float sm[8];
    __shared__ float ssx;
    if ((t & 31) == 0) sm[t >> 5] = m;
    __syncthreads();
    if (t == 0) {
        float mm = sm[0];
        #pragma unroll
        for (int i = 1; i < 8; i++) mm = fmaxf(mm, sm[i]);
        float sx = __fdiv_rn(fmaxf(mm, EPSF), 127.f);
        g_sx[row] = sx;
        ssx = sx;
    }
    __syncthreads();
    float sx = ssx;
    char4* out = (char4*)(g_xq + (size_t)row * HDIM);
    #pragma unroll
    for (int i = 0; i < 4; i++) {
        float4 u = v[i];
        char4 o;
        o.x = q8(u.x, sx); o.y = q8(u.y, sx); o.z = q8(u.z, sx); o.w = q8(u.w, sx);
        out[t * 4 + i] = o;
    }
}

__global__ void k_quanth() {
    int row = blockIdx.x;
    float sh = __fdiv_rn(fmaxf(__uint_as_float(g_rowmax[row]), EPSF), 127.f);
    if (threadIdx.x == 0) g_sh[row] = sh;
    const float4* hr = (const float4*)(g_h + (size_t)row * IDIM);
    char4* out = (char4*)(g_hq + (size_t)row * IDIM);
    for (int i = threadIdx.x; i < IDIM / 4; i += blockDim.x) {
        float4 u = hr[i];
        char4 o;
        o.x = q8(u.x, sh); o.y = q8(u.y, sh); o.z = q8(u.z, sh); o.w = q8(u.w, sh);
        out[i] = o;
    }
}

// ====== hybrid GEMM, 2 CTAs/SM: 256 threads; warps 0-3 = mma ([0,T)), warps 4-7 = dp4a ([T,NK))
// D[128x64] tile. smem: [0,3S) mma ring | [3S,6S) dp4a ring (overlaid by s32 partial tile after loop)
// dp4a A-ring uses an in-row chunk ROTATION ((cc + r/8) & 3) -> conflict-free a-loads, no overflow.
template <int MODE>
__global__ __launch_bounds__(256, 2) void k_gemm(float* __restrict__ outp) {
    constexpr int K = MODE ? IDIM : HDIM;
    constexpr int N = MODE ? HDIM : IDIM;
    constexpr int NK = K / 64;
    constexpr int T = MODE ? 144 : 36;      // tensor K-chunks (R5-optimal ratio)
    constexpr int ND = NK - T;
    constexpr int ASZ = 128 * 80;           // 10240
    constexpr int STAGE = ASZ + 64 * 80;    // 15360
    const signed char* Ag = MODE ? g_hq : g_xq;
    const signed char* Bg = MODE ? g_wq2 : g_wq1;
    float* Out = MODE ? outp : g_h;
    const float* srow = MODE ? g_sh : g_sx;

    extern __shared__ __align__(128) char smem[];
    uint32_t smbase = smem_u32(smem);
    int* Ssm = (int*)(smem + 3 * STAGE);    // overlays dp4a ring after its loop; 128 x 68 s32

    int tid = threadIdx.x;
    int gt = tid & 127;
    bool is_mma = tid < 128;

    int mt = MODE ? blockIdx.y : blockIdx.x;
    int nt = MODE ? blockIdx.x : blockIdx.y;
    int mb = mt * 128, nb = nt * 64;

    uint32_t gbase = smbase + (is_mma ? 0u : (uint32_t)(3 * STAGE));
    auto load_stage = [&](int s, int kc) {
        uint32_t base = gbase + s * STAGE;
        const signed char* ag = Ag + (size_t)mb * K + (size_t)kc * 64;
        const signed char* bg = Bg + (size_t)nb * K + (size_t)kc * 64;
        #pragma unroll
        for (int i = 0; i < 4; i++) {       // A: 128 rows x 4 chunks of 16B
            int c = gt + i * 128;
            int r = c >> 2, cc = c & 3;
            int cc2 = is_mma ? cc : ((cc + (r >> 3)) & 3);   // rotation stays in-row
            CP_ASYNC16(base + r * 80 + cc2 * 16, ag + (size_t)r * K + cc * 16);
        }
        #pragma unroll
        for (int i = 0; i < 2; i++) {       // B: 64 rows x 4 chunks
            int c = gt + i * 128;
            int r = c >> 2, cc = c & 3;
            CP_ASYNC16(base + ASZ + r * 80 + cc * 16, bg + (size_t)r * K + cc * 16);
        }
        CP_COMMIT();
    };

    int acc[4][4][4];  // mma accumulators (mma group only)

    if (is_mma) {
        // ---------------- tensor group: 4 warps, 64x32 warp tiles ----------------
        int wid = gt >> 5, lane = gt & 31;
        int wm = wid & 1, wn = wid >> 1;    // 2 x 2 warp grid
        int rq = lane & 7, q = lane >> 3;
        #pragma unroll
        for (int i = 0; i < 4; i++)
            #pragma unroll
            for (int j = 0; j < 4; j++)
                #pragma unroll
                for (int c = 0; c < 4; c++) acc[i][j][c] = 0;

        int lrow = rq + (q & 1) * 8;
        int lcol = (q >> 1) * 16;
        int aoff[4], boff[2];
        #pragma unroll
        for (int m = 0; m < 4; m++) aoff[m] = (wm * 64 + m * 16 + lrow) * 80 + lcol;
        #pragma unroll
        for (int bt = 0; bt < 2; bt++) boff[bt] = ASZ + (wn * 32 + bt * 16 + lrow) * 80 + lcol;

        load_stage(0, 0);
        load_stage(1, 1);
        for (int k = 0; k < T; k++) {
            if (k < T - 1) { CP_WAIT(1); } else { CP_WAIT(0); }
            BARRIER(1);   // arriving here also proves compute k-1 done before stage reuse
            if (k + 2 < T) load_stage((k + 2) % 3, k + 2);

            uint32_t sA = gbase + (k % 3) * STAGE;
            #pragma unroll
            for (int ks = 0; ks < 2; ks++) {
                uint32_t af[4][4], bf[2][4];
                #pragma unroll
                for (int m = 0; m < 4; m++)
                    LDSM4(af[m][0], af[m][1], af[m][2], af[m][3], sA + aoff[m] + ks * 32);
                #pragma unroll
                for (int bt = 0; bt < 2; bt++)
                    LDSM4(bf[bt][0], bf[bt][1], bf[bt][2], bf[bt][3], sA + boff[bt] + ks * 32);
                #pragma unroll
                for (int m = 0; m < 4; m++)
                    #pragma unroll
                    for (int bt = 0; bt < 2; bt++) {
                        MMA_S8(acc[m][bt * 2 + 0], af[m], bf[bt][0], bf[bt][2]);
                        MMA_S8(acc[m][bt * 2 + 1], af[m], bf[bt][1], bf[bt][3]);
                    }
            }
        }
    } else {
        // ---------------- dp4a group: 4 warps, 8x8 outputs/thread ----------------
        int r8 = (gt >> 3) * 8;             // 16 row-blocks of 8
        int c0 = gt & 7;                    // cols = c0 + 8*j2
        int rot = (r8 >> 3) & 3;            // chunk rotation for this thread's rows
        int dacc[8][8];
        #pragma unroll
        for (int i = 0; i < 8; i++)
            #pragma unroll
            for (int j = 0; j < 8; j++) dacc[i][j] = 0;

        load_stage(0, T);
        load_stage(1, T + 1);
        for (int k = 0; k < ND; k++) {
            if (k < ND - 1) { CP_WAIT(1); } else { CP_WAIT(0); }
            BARRIER(2);
            if (k + 2 < ND) load_stage((k + 2) % 3, T + k + 2);

            uint32_t sA = gbase + (k % 3) * STAGE;
            uint32_t sB = sA + ASZ;
            #pragma unroll
            for (int cp = 0; cp < 8; cp++) {
                int aoffc = (((cp >> 1) + rot) & 3) * 16 + (cp & 1) * 8;  // rotated chunk addr
                uint32_t b0[8], b1[8];
                #pragma unroll
                for (int j2 = 0; j2 < 8; j2++)
                    LDS64(b0[j2], b1[j2], sB + (c0 + 8 * j2) * 80 + cp * 8);
                #pragma unroll
                for (int i = 0; i < 8; i++) {
                    uint32_t a0, a1;
                    LDS64(a0, a1, sA + (r8 + i) * 80 + aoffc);
                    #pragma unroll
                    for (int j2 = 0; j2 < 8; j2++) {
                        dacc[i][j2] = __dp4a((int)a0, (int)b0[j2], dacc[i][j2]);
                        dacc[i][j2] = __dp4a((int)a1, (int)b1[j2], dacc[i][j2]);
                    }
                }
            }
        }
        BARRIER(2);   // all dp4a warps done reading ring before overlaying with partials
        #pragma unroll
        for (int i = 0; i < 8; i++)
            #pragma unroll
            for (int j2 = 0; j2 < 8; j2++)
                Ssm[(r8 + i) * 68 + c0 + 8 * j2] = dacc[i][j2];
    }

    __syncthreads();   // join: dp4a partials visible

    if (is_mma) {
        // ---------------- epilogue: combine + dequant (+gelu/rowmax) ----------------
        int wid = gt >> 5, lane = gt & 31;
        int wm = wid & 1, wn = wid >> 1;
        int g = lane >> 2, tig = lane & 3;
        float sw = g_swf[MODE];
        #pragma unroll
        for (int m = 0; m < 4; m++) {
            int rL0 = wm * 64 + m * 16 + g;
            int row0 = mb + rL0;
            int row1 = row0 + 8;
            float s0 = srow[row0] * sw;
            float s1 = srow[row1] * sw;
            float mx0 = 0.f, mx1 = 0.f;
            #pragma unroll
            for (int j = 0; j < 4; j++) {
                int colL = wn * 32 + j * 8 + tig * 2;
                int2 d0 = *(const int2*)(Ssm + rL0 * 68 + colL);
                int2 d1 = *(const int2*)(Ssm + (rL0 + 8) * 68 + colL);
                float v00 = (float)(acc[m][j][0] + d0.x) * s0;
                float v01 = (float)(acc[m][j][1] + d0.y) * s0;
                float v10 = (float)(acc[m][j][2] + d1.x) * s1;
                float v11 = (float)(acc[m][j][3] + d1.y) * s1;
                if (MODE == 0) {
                    v00 = 0.5f * v00 * (1.f + erff(v00 * 0.70710678118654752f));
                    v01 = 0.5f * v01 * (1.f + erff(v01 * 0.70710678118654752f));
                    v10 = 0.5f * v10 * (1.f + erff(v10 * 0.70710678118654752f));
                    v11 = 0.5f * v11 * (1.f + erff(v11 * 0.70710678118654752f));
                    mx0 = fmaxf(mx0, fmaxf(fabsf(v00), fabsf(v01)));
                    mx1 = fmaxf(mx1, fmaxf(fabsf(v10), fabsf(v11)));
                }
                *(float2*)(Out + (size_t)row0 * N + nb + colL) = make_float2(v00, v01);
                *(float2*)(Out + (size_t)row1 * N + nb + colL) = make_float2(v10, v11);
            }
            if (MODE == 0) {
                #pragma unroll
                for (int o = 1; o < 4; o <<= 1) {
                    mx0 = fmaxf(mx0, __shfl_xor_sync(0xFFFFFFFFu, mx0, o));
                    mx1 = fmaxf(mx1, __shfl_xor_sync(0xFFFFFFFFu, mx1, o));
                }
                if (tig == 0) {
                    atomicMax(&g_rowmax[row0], __float_as_uint(mx0));
                    atomicMax(&g_rowmax[row1], __float_as_uint(mx1));
                }
            }
        }
    }
}

// ---------------- launch ----------------
extern "C" void kernel_launch(void* const* d_in, const int* in_sizes, int n_in,
                              void* d_out, int out_size) {
    const float* x  = (const float*)d_in[0];
    const float* W1 = (const float*)d_in[1];
    const float* W2 = (const float*)d_in[2];
    float* out = (float*)d_out;

    const int SMEM = 6 * 15360;   // 92160; 2 CTAs/SM
    cudaFuncSetAttribute(k_gemm<0>, cudaFuncAttributeMaxDynamicSharedMemorySize, SMEM);
    cudaFuncSetAttribute(k_gemm<1>, cudaFuncAttributeMaxDynamicSharedMemorySize, SMEM);

    k_abssum<<<2048, 256>>>((const float4*)W1, 0);   // 0
    k_quantw<0><<<4096, 256>>>((const float4*)W1);   // 1
    k_quantx<<<MTOT, 256>>>(x);                      // 2 (also zeroes rowmax)
    k_gemm<0><<<dim3(64, 256), 256, SMEM>>>(out);    // 3  <- ncu capture slot
    k_quanth<<<MTOT, 256>>>();                       // 4
    k_abssum<<<2048, 256>>>((const float4*)W2, 1);   // 5
    k_quantw<1><<<4096, 256>>>((const float4*)W2);   // 6
    k_gemm<1><<<dim3(64, 64), 256, SMEM>>>(out);     // 7
}

// round 12
// speedup vs baseline: 1.7699x; 1.0058x over previous
#include <cuda_runtime.h>
#include <cuda_bf16.h>
#include <cstdint>
#include <cstddef>

#define MTOT 8192
#define HDIM 4096
#define IDIM 16384
#define WCNT 67108864ULL
#define EPSF 1e-5f

// ---------------- scratch (device globals; no allocations) ----------------
__device__ __align__(16) signed char g_wq1[(size_t)IDIM * HDIM];  // 64MB
__device__ __align__(16) signed char g_wq2[(size_t)IDIM * HDIM];  // 64MB
__device__ __align__(16) signed char g_xq[(size_t)MTOT * HDIM];   // 32MB
__device__ __align__(16) signed char g_hq[(size_t)MTOT * IDIM];   // 128MB
__device__ __align__(16) float g_h[(size_t)MTOT * IDIM];          // 512MB
__device__ float g_sx[MTOT];
__device__ float g_sh[MTOT];
__device__ unsigned int g_rowmax[MTOT];
__device__ unsigned long long g_wpart[2][2048];
__device__ float g_swf[2];

// ---------------- PTX helpers ----------------
static __device__ __forceinline__ uint32_t smem_u32(const void* p) {
    uint32_t a;
    asm("{ .reg .u64 t; cvta.to.shared.u64 t, %1; cvt.u32.u64 %0, t; }" : "=r"(a) : "l"(p));
    return a;
}
#define CP_ASYNC16(dst, src) \
    asm volatile("cp.async.cg.shared.global [%0], [%1], 16;" :: "r"(dst), "l"(src))
#define CP_COMMIT() asm volatile("cp.async.commit_group;" ::: "memory")
#define CP_WAIT(n)  asm volatile("cp.async.wait_group " #n ";" ::: "memory")
#define BARRIER(id) asm volatile("bar.sync %0, 128;" :: "r"(id) : "memory")

#define LDSM4(r0, r1, r2, r3, addr) \
    asm volatile("ldmatrix.sync.aligned.m8n8.x4.shared.b16 {%0,%1,%2,%3}, [%4];" \
                 : "=r"(r0), "=r"(r1), "=r"(r2), "=r"(r3) : "r"(addr))

#define MMA_S8(d, a, b0, b1) \
    asm volatile("mma.sync.aligned.m16n8k32.row.col.s32.s8.s8.s32 " \
                 "{%0,%1,%2,%3}, {%4,%5,%6,%7}, {%8,%9}, {%0,%1,%2,%3};" \
                 : "+r"((d)[0]), "+r"((d)[1]), "+r"((d)[2]), "+r"((d)[3]) \
                 : "r"((a)[0]), "r"((a)[1]), "r"((a)[2]), "r"((a)[3]), \
                   "r"(b0), "r"(b1))

#define LDS64(r0, r1, addr) \
    asm volatile("ld.shared.v2.u32 {%0,%1},[%2];" : "=r"(r0), "=r"(r1) : "r"(addr))

// ---------------- elementwise kernels ----------------
__global__ void k_abssum(const float4* __restrict__ w, int which) {
    unsigned long long a0 = 0, a1 = 0, a2 = 0, a3 = 0;   // 4-way ILP
    size_t n4 = WCNT / 4;
    for (size_t i = (size_t)blockIdx.x * blockDim.x + threadIdx.x; i < n4;
         i += (size_t)gridDim.x * blockDim.x) {
        float4 v = w[i];
        a0 += (unsigned long long)llrintf(fabsf(v.x) * 1099511627776.f);
        a1 += (unsigned long long)llrintf(fabsf(v.y) * 1099511627776.f);
        a2 += (unsigned long long)llrintf(fabsf(v.z) * 1099511627776.f);
        a3 += (unsigned long long)llrintf(fabsf(v.w) * 1099511627776.f);
    }
    unsigned long long acc = (a0 + a1) + (a2 + a3);
    for (int o = 16; o > 0; o >>= 1)
        acc += __shfl_down_sync(0xFFFFFFFFu, acc, o);
    __shared__ unsigned long long s[8];
    if ((threadIdx.x & 31) == 0) s[threadIdx.x >> 5] = acc;
    __syncthreads();
    if (threadIdx.x == 0) {
        unsigned long long t = 0;
        #pragma unroll
        for (int i = 0; i < 8; i++) t += s[i];
        g_wpart[which][blockIdx.x] = t;
    }
}

static __device__ __forceinline__ float reduce_sw(int which) {
    unsigned long long acc = 0;
    #pragma unroll
    for (int i = 0; i < 8; i++)
        acc += g_wpart[which][threadIdx.x * 8 + i];
    for (int o = 16; o > 0; o >>= 1)
        acc += __shfl_down_sync(0xFFFFFFFFu, acc, o);
    __shared__ unsigned long long s[8];
    __shared__ float sws;
    if ((threadIdx.x & 31) == 0) s[threadIdx.x >> 5] = acc;
    __syncthreads();
    if (threadIdx.x == 0) {
        unsigned long long t = 0;
        #pragma unroll
        for (int i = 0; i < 8; i++) t += s[i];
        double mean = (double)t * (1.0 / 1099511627776.0) / 67108864.0;
        sws = (float)fmax(mean, (double)EPSF);
    }
    __syncthreads();
    return sws;
}

template <int WHICH>
__global__ void k_quantw(const float4* __restrict__ w) {
    float sw = reduce_sw(WHICH);
    if (blockIdx.x == 0 && threadIdx.x == 0) g_swf[WHICH] = sw;
    char4* q = (char4*)(WHICH ? g_wq2 : g_wq1);
    size_t n4 = WCNT / 4;
    for (size_t i = (size_t)blockIdx.x * blockDim.x + threadIdx.x; i < n4;
         i += (size_t)gridDim.x * blockDim.x) {
        float4 v = w[i];
        char4 o;
        o.x = (signed char)(int)fminf(fmaxf(rintf(__fdiv_rn(v.x, sw)), -1.f), 1.f);
        o.y = (signed char)(int)fminf(fmaxf(rintf(__fdiv_rn(v.y, sw)), -1.f), 1.f);
        o.z = (signed char)(int)fminf(fmaxf(rintf(__fdiv_rn(v.z, sw)), -1.f), 1.f);
        o.w = (signed char)(int)fminf(fmaxf(rintf(__fdiv_rn(v.w, sw)), -1.f), 1.f);
        q[i] = o;
    }
}

static __device__ __forceinline__ signed char q8(float x, float s) {
    return (signed char)(int)fminf(fmaxf(rintf(__fdiv_rn(x, s)), -128.f), 127.f);
}

__global__ void k_quantx(const float* __restrict__ x) {
    int row = blockIdx.x;
    int t = threadIdx.x;
    if (t == 0) g_rowmax[row] = 0u;
    const float4* xr = (const float4*)(x + (size_t)row * HDIM);
    float4 v[4];
    float m = 0.f;
    #pragma unroll
    for (int i = 0; i < 4; i++) {
        v[i] = xr[t * 4 + i];
        m = fmaxf(m, fmaxf(fmaxf(fabsf(v[i].x), fabsf(v[i].y)),
                           fmaxf(fabsf(v[i].z), fabsf(v[i].w))));
    }
    for (int o = 16; o > 0; o >>= 1)
        m = fmaxf(m, __shfl_xor_sync(0xFFFFFFFFu, m, o));
    __shared__ float sm[8];
    __shared__ float ssx;
    if ((t & 31) == 0) sm[t >> 5] = m;
    __syncthreads();
    if (t == 0) {
        float mm = sm[0];
        #pragma unroll
        for (int i = 1; i < 8; i++) mm = fmaxf(mm, sm[i]);
        float sx = __fdiv_rn(fmaxf(mm, EPSF), 127.f);
        g_sx[row] = sx;
        ssx = sx;
    }
    __syncthreads();
    float sx = ssx;
    char4* out = (char4*)(g_xq + (size_t)row * HDIM);
    #pragma unroll
    for (int i = 0; i < 4; i++) {
        float4 u = v[i];
        char4 o;
        o.x = q8(u.x, sx); o.y = q8(u.y, sx); o.z = q8(u.z, sx); o.w = q8(u.w, sx);
        out[t * 4 + i] = o;
    }
}

__global__ void k_quanth() {
    int row = blockIdx.x;
    float sh = __fdiv_rn(fmaxf(__uint_as_float(g_rowmax[row]), EPSF), 127.f);
    if (threadIdx.x == 0) g_sh[row] = sh;
    const float4* hr = (const float4*)(g_h + (size_t)row * IDIM);
    char4* out = (char4*)(g_hq + (size_t)row * IDIM);
    for (int i = threadIdx.x; i < IDIM / 4; i += blockDim.x) {
        float4 u = hr[i];
        char4 o;
        o.x = q8(u.x, sh); o.y = q8(u.y, sh); o.z = q8(u.z, sh); o.w = q8(u.w, sh);
        out[i] = o;
    }
}

// ====== hybrid GEMM, 2 CTAs/SM: 256 threads; warps 0-3 = mma ([0,T)), warps 4-7 = dp4a ([T,NK))
// D[128x64] tile. smem: [0,4S) mma ring (4-stage) | [4S,7S) dp4a ring (3-stage; s32 partials overlay)
// mma mainloop is fragment-level software-pipelined. Sync protocol (race-free):
//   every LDSM of stage s happens only after CP_WAIT proving own writes of s done, THEN a barrier
//   (so all threads' writes are visible); every load_stage overwrite of a stage is separated from
//   its last reader by the previous iteration's barrier.
template <int MODE>
__global__ __launch_bounds__(256, 2) void k_gemm(float* __restrict__ outp) {
    constexpr int K = MODE ? IDIM : HDIM;
    constexpr int N = MODE ? HDIM : IDIM;
    constexpr int NK = K / 64;
    constexpr int T = MODE ? 144 : 36;      // tensor K-chunks
    constexpr int ND = NK - T;
    constexpr int ASZ = 128 * 80;           // 10240
    constexpr int STAGE = ASZ + 64 * 80;    // 15360
    const signed char* Ag = MODE ? g_hq : g_xq;
    const signed char* Bg = MODE ? g_wq2 : g_wq1;
    float* Out = MODE ? outp : g_h;
    const float* srow = MODE ? g_sh : g_sx;

    extern __shared__ __align__(128) char smem[];
    uint32_t smbase = smem_u32(smem);
    int* Ssm = (int*)(smem + 4 * STAGE);    // overlays dp4a ring after its loop; 128 x 68 s32

    int tid = threadIdx.x;
    int gt = tid & 127;
    bool is_mma = tid < 128;

    int mt = MODE ? blockIdx.y : blockIdx.x;
    int nt = MODE ? blockIdx.x : blockIdx.y;
    int mb = mt * 128, nb = nt * 64;

    uint32_t gbase = smbase + (is_mma ? 0u : (uint32_t)(4 * STAGE));
    auto load_stage = [&](int s, int kc) {
        uint32_t base = gbase + s * STAGE;
        const signed char* ag = Ag + (size_t)mb * K + (size_t)kc * 64;
        const signed char* bg = Bg + (size_t)nb * K + (size_t)kc * 64;
        #pragma unroll
        for (int i = 0; i < 4; i++) {       // A: 128 rows x 4 chunks of 16B
            int c = gt + i * 128;
            int r = c >> 2, cc = c & 3;
            int cc2 = is_mma ? cc : ((cc + (r >> 3)) & 3);   // dp4a in-row rotation
            CP_ASYNC16(base + r * 80 + cc2 * 16, ag + (size_t)r * K + cc * 16);
        }
        #pragma unroll
        for (int i = 0; i < 2; i++) {       // B: 64 rows x 4 chunks
            int c = gt + i * 128;
            int r = c >> 2, cc = c & 3;
            CP_ASYNC16(base + ASZ + r * 80 + cc * 16, bg + (size_t)r * K + cc * 16);
        }
        CP_COMMIT();
    };

    int acc[4][4][4];  // mma accumulators (mma group only)

    if (is_mma) {
        // ---------------- tensor group: 4 warps, 64x32 warp tiles, 4-stage pipelined ----
        int wid = gt >> 5, lane = gt & 31;
        int wm = wid & 1, wn = wid >> 1;    // 2 x 2 warp grid
        int rq = lane & 7, q = lane >> 3;
        #pragma unroll
        for (int i = 0; i < 4; i++)
            #pragma unroll
            for (int j = 0; j < 4; j++)
                #pragma unroll
                for (int c = 0; c < 4; c++) acc[i][j][c] = 0;

        int lrow = rq + (q & 1) * 8;
        int lcol = (q >> 1) * 16;
        int aoff[4], boff[2];
        #pragma unroll
        for (int m = 0; m < 4; m++) aoff[m] = (wm * 64 + m * 16 + lrow) * 80 + lcol;
        #pragma unroll
        for (int bt = 0; bt < 2; bt++) boff[bt] = ASZ + (wn * 32 + bt * 16 + lrow) * 80 + lcol;

        load_stage(0, 0);
        load_stage(1, 1);
        load_stage(2, 2);
        CP_WAIT(2);                         // own stage-0 writes done
        BARRIER(1);                         // everyone's stage-0 writes visible

        uint32_t af0[4][4], bf0[2][4], af1[4][4], bf1[2][4];
        #pragma unroll
        for (int m = 0; m < 4; m++)
            LDSM4(af0[m][0], af0[m][1], af0[m][2], af0[m][3], gbase + aoff[m]);
        #pragma unroll
        for (int bt = 0; bt < 2; bt++)
            LDSM4(bf0[bt][0], bf0[bt][1], bf0[bt][2], bf0[bt][3], gbase + boff[bt]);

        for (int k = 0; k < T; k++) {
            uint32_t sA = gbase + (k & 3) * STAGE;
            // ks1 fragments of chunk k (stage k resident & visible since its pre-read barrier)
            #pragma unroll
            for (int m = 0; m < 4; m++)
                LDSM4(af1[m][0], af1[m][1], af1[m][2], af1[m][3], sA + aoff[m] + 32);
            #pragma unroll
            for (int bt = 0; bt < 2; bt++)
                LDSM4(bf1[bt][0], bf1[bt][1], bf1[bt][2], bf1[bt][3], sA + boff[bt] + 32);
            // MMA burst ks0
            #pragma unroll
            for (int m = 0; m < 4; m++)
                #pragma unroll
                for (int bt = 0; bt < 2; bt++) {
                    MMA_S8(acc[m][bt * 2 + 0], af0[m], bf0[bt][0], bf0[bt][2]);
                    MMA_S8(acc[m][bt * 2 + 1], af0[m], bf0[bt][1], bf0[bt][3]);
                }
            // commit next stage; graduated wait proves own stage-(k+1) writes done
            // (write target (k+3)&3=(k-1)&3: its last reader was iter k-1's loop-top LDSM,
            //  separated from this write by iter k-1's BARRIER below)
            if (k + 3 < T)      { load_stage((k + 3) & 3, k + 3); CP_WAIT(2); }
            else if (k + 2 < T) { CP_WAIT(1); }
            else if (k + 1 < T) { CP_WAIT(0); }
            if (k + 1 < T) {
                BARRIER(1);     // all threads past their wait -> stage k+1 fully visible
                uint32_t sN = gbase + ((k + 1) & 3) * STAGE;
                #pragma unroll
                for (int m = 0; m < 4; m++)
                    LDSM4(af0[m][0], af0[m][1], af0[m][2], af0[m][3], sN + aoff[m]);
                #pragma unroll
                for (int bt = 0; bt < 2; bt++)
                    LDSM4(bf0[bt][0], bf0[bt][1], bf0[bt][2], bf0[bt][3], sN + boff[bt]);
            }
            // MMA burst ks1
            #pragma unroll
            for (int m = 0; m < 4; m++)
                #pragma unroll
                for (int bt = 0; bt < 2; bt++) {
                    MMA_S8(acc[m][bt * 2 + 0], af1[m], bf1[bt][0], bf1[bt][2]);
                    MMA_S8(acc[m][bt * 2 + 1], af1[m], bf1[bt][1], bf1[bt][3]);
                }
        }
    } else {
        // ---------------- dp4a group: 4 warps, 8x8 outputs/thread, 3-stage ----------------
        int r8 = (gt >> 3) * 8;             // 16 row-blocks of 8
        int c0 = gt & 7;                    // cols = c0 + 8*j2
        int rot = (r8 >> 3) & 3;            // chunk rotation for this thread's rows
        int dacc[8][8];
        #pragma unroll
        for (int i = 0; i < 8; i++)
            #pragma unroll
            for (int j = 0; j < 8; j++) dacc[i][j] = 0;

        load_stage(0, T);
        load_stage(1, T + 1);
        for (int k = 0; k < ND; k++) {
            if (k < ND - 1) { CP_WAIT(1); } else { CP_WAIT(0); }
            BARRIER(2);
            if (k + 2 < ND) load_stage((k + 2) % 3, T + k + 2);

            uint32_t sA = gbase + (k % 3) * STAGE;
            uint32_t sB = sA + ASZ;
            #pragma unroll
            for (int cp = 0; cp < 8; cp++) {
                int aoffc = (((cp >> 1) + rot) & 3) * 16 + (cp & 1) * 8;  // rotated chunk addr
                uint32_t b0[8], b1[8];
                #pragma unroll
                for (int j2 = 0; j2 < 8; j2++)
                    LDS64(b0[j2], b1[j2], sB + (c0 + 8 * j2) * 80 + cp * 8);
                #pragma unroll
                for (int i = 0; i < 8; i++) {
                    uint32_t a0, a1;
                    LDS64(a0, a1, sA + (r8 + i) * 80 + aoffc);
                    #pragma unroll
                    for (int j2 = 0; j2 < 8; j2++) {
                        dacc[i][j2] = __dp4a((int)a0, (int)b0[j2], dacc[i][j2]);
                        dacc[i][j2] = __dp4a((int)a1, (int)b1[j2], dacc[i][j2]);
                    }
                }
            }
        }
        BARRIER(2);   // all dp4a warps done reading ring before overlaying with partials
        #pragma unroll
        for (int i = 0; i < 8; i++)
            #pragma unroll
            for (int j2 = 0; j2 < 8; j2++)
                Ssm[(r8 + i) * 68 + c0 + 8 * j2] = dacc[i][j2];
    }

    __syncthreads();   // join: dp4a partials visible

    if (is_mma) {
        // ---------------- epilogue: combine + dequant (+gelu/rowmax) ----------------
        int wid = gt >> 5, lane = gt & 31;
        int wm = wid & 1, wn = wid >> 1;
        int g = lane >> 2, tig = lane & 3;
        float sw = g_swf[MODE];
        #pragma unroll
        for (int m = 0; m < 4; m++) {
            int rL0 = wm * 64 + m * 16 + g;
            int row0 = mb + rL0;
            int row1 = row0 + 8;
            float s0 = srow[row0] * sw;
            float s1 = srow[row1] * sw;
            float mx0 = 0.f, mx1 = 0.f;
            #pragma unroll
            for (int j = 0; j < 4; j++) {
                int colL = wn * 32 + j * 8 + tig * 2;
                int2 d0 = *(const int2*)(Ssm + rL0 * 68 + colL);
                int2 d1 = *(const int2*)(Ssm + (rL0 + 8) * 68 + colL);
                float v00 = (float)(acc[m][j][0] + d0.x) * s0;
                float v01 = (float)(acc[m][j][1] + d0.y) * s0;
                float v10 = (float)(acc[m][j][2] + d1.x) * s1;
                float v11 = (float)(acc[m][j][3] + d1.y) * s1;
                if (MODE == 0) {
                    v00 = 0.5f * v00 * (1.f + erff(v00 * 0.70710678118654752f));
                    v01 = 0.5f * v01 * (1.f + erff(v01 * 0.70710678118654752f));
                    v10 = 0.5f * v10 * (1.f + erff(v10 * 0.70710678118654752f));
                    v11 = 0.5f * v11 * (1.f + erff(v11 * 0.70710678118654752f));
                    mx0 = fmaxf(mx0, fmaxf(fabsf(v00), fabsf(v01)));
                    mx1 = fmaxf(mx1, fmaxf(fabsf(v10), fabsf(v11)));
                }
                *(float2*)(Out + (size_t)row0 * N + nb + colL) = make_float2(v00, v01);
                *(float2*)(Out + (size_t)row1 * N + nb + colL) = make_float2(v10, v11);
            }
            if (MODE == 0) {
                #pragma unroll
                for (int o = 1; o < 4; o <<= 1) {
                    mx0 = fmaxf(mx0, __shfl_xor_sync(0xFFFFFFFFu, mx0, o));
                    mx1 = fmaxf(mx1, __shfl_xor_sync(0xFFFFFFFFu, mx1, o));
                }
                if (tig == 0) {
                    atomicMax(&g_rowmax[row0], __float_as_uint(mx0));
                    atomicMax(&g_rowmax[row1], __float_as_uint(mx1));
                }
            }
        }
    }
}

// ---------------- launch ----------------
extern "C" void kernel_launch(void* const* d_in, const int* in_sizes, int n_in,
                              void* d_out, int out_size) {
    const float* x  = (const float*)d_in[0];
    const float* W1 = (const float*)d_in[1];
    const float* W2 = (const float*)d_in[2];
    float* out = (float*)d_out;

    const int SMEM = 7 * 15360;   // 107520; 2 CTAs/SM (215KB < 228KB)
    cudaFuncSetAttribute(k_gemm<0>, cudaFuncAttributeMaxDynamicSharedMemorySize, SMEM);
    cudaFuncSetAttribute(k_gemm<1>, cudaFuncAttributeMaxDynamicSharedMemorySize, SMEM);

    k_abssum<<<2048, 256>>>((const float4*)W1, 0);   // 0
    k_quantw<0><<<4096, 256>>>((const float4*)W1);   // 1
    k_quantx<<<MTOT, 256>>>(x);                      // 2 (also zeroes rowmax)
    k_gemm<0><<<dim3(64, 256), 256, SMEM>>>(out);    // 3  <- ncu capture slot
    k_quanth<<<MTOT, 256>>>();                       // 4
    k_abssum<<<2048, 256>>>((const float4*)W2, 1);   // 5
    k_quantw<1><<<4096, 256>>>((const float4*)W2);   // 6
    k_gemm<1><<<dim3(64, 64), 256, SMEM>>>(out);     // 7
}

// round 13
// speedup vs baseline: 1.7736x; 1.0021x over previous
#include <cuda_runtime.h>
#include <cuda_bf16.h>
#include <cstdint>
#include <cstddef>

#define MTOT 8192
#define HDIM 4096
#define IDIM 16384
#define WCNT 67108864ULL
#define EPSF 1e-5f

// ---------------- scratch (device globals; no allocations) ----------------
__device__ __align__(16) signed char g_wq1[(size_t)IDIM * HDIM];  // 64MB
__device__ __align__(16) signed char g_wq2[(size_t)IDIM * HDIM];  // 64MB
__device__ __align__(16) signed char g_xq[(size_t)MTOT * HDIM];   // 32MB
__device__ __align__(16) signed char g_hq[(size_t)MTOT * IDIM];   // 128MB
__device__ __align__(16) float g_h[(size_t)MTOT * IDIM];          // 512MB
__device__ float g_sx[MTOT];
__device__ float g_sh[MTOT];
__device__ unsigned int g_rowmax[MTOT];
__device__ unsigned long long g_wpart[2][2048];
__device__ float g_swf[2];

// ---------------- PTX helpers ----------------
static __device__ __forceinline__ uint32_t smem_u32(const void* p) {
    uint32_t a;
    asm("{ .reg .u64 t; cvta.to.shared.u64 t, %1; cvt.u32.u64 %0, t; }" : "=r"(a) : "l"(p));
    return a;
}
#define CP_ASYNC16(dst, src) \
    asm volatile("cp.async.cg.shared.global [%0], [%1], 16;" :: "r"(dst), "l"(src))
#define CP_COMMIT() asm volatile("cp.async.commit_group;" ::: "memory")
#define CP_WAIT(n)  asm volatile("cp.async.wait_group " #n ";" ::: "memory")
#define BARRIER(id) asm volatile("bar.sync %0, 128;" :: "r"(id) : "memory")

#define LDSM4(r0, r1, r2, r3, addr) \
    asm volatile("ldmatrix.sync.aligned.m8n8.x4.shared.b16 {%0,%1,%2,%3}, [%4];" \
                 : "=r"(r0), "=r"(r1), "=r"(r2), "=r"(r3) : "r"(addr))

#define MMA_S8(d, a, b0, b1) \
    asm volatile("mma.sync.aligned.m16n8k32.row.col.s32.s8.s8.s32 " \
                 "{%0,%1,%2,%3}, {%4,%5,%6,%7}, {%8,%9}, {%0,%1,%2,%3};" \
                 : "+r"((d)[0]), "+r"((d)[1]), "+r"((d)[2]), "+r"((d)[3]) \
                 : "r"((a)[0]), "r"((a)[1]), "r"((a)[2]), "r"((a)[3]), \
                   "r"(b0), "r"(b1))

#define LDS64(r0, r1, addr) \
    asm volatile("ld.shared.v2.u32 {%0,%1},[%2];" : "=r"(r0), "=r"(r1) : "r"(addr))
#define LDS128(r0, r1, r2, r3, addr) \
    asm volatile("ld.shared.v4.u32 {%0,%1,%2,%3},[%4];" \
                 : "=r"(r0), "=r"(r1), "=r"(r2), "=r"(r3) : "r"(addr))

// ---------------- elementwise kernels ----------------
__global__ void k_abssum(const float4* __restrict__ w, int which) {
    unsigned long long a0 = 0, a1 = 0, a2 = 0, a3 = 0;   // 4-way ILP
    size_t n4 = WCNT / 4;
    for (size_t i = (size_t)blockIdx.x * blockDim.x + threadIdx.x; i < n4;
         i += (size_t)gridDim.x * blockDim.x) {
        float4 v = w[i];
        a0 += (unsigned long long)llrintf(fabsf(v.x) * 1099511627776.f);
        a1 += (unsigned long long)llrintf(fabsf(v.y) * 1099511627776.f);
        a2 += (unsigned long long)llrintf(fabsf(v.z) * 1099511627776.f);
        a3 += (unsigned long long)llrintf(fabsf(v.w) * 1099511627776.f);
    }
    unsigned long long acc = (a0 + a1) + (a2 + a3);
    for (int o = 16; o > 0; o >>= 1)
        acc += __shfl_down_sync(0xFFFFFFFFu, acc, o);
    __shared__ unsigned long long s[8];
    if ((threadIdx.x & 31) == 0) s[threadIdx.x >> 5] = acc;
    __syncthreads();
    if (threadIdx.x == 0) {
        unsigned long long t = 0;
        #pragma unroll
        for (int i = 0; i < 8; i++) t += s[i];
        g_wpart[which][blockIdx.x] = t;
    }
}

static __device__ __forceinline__ float reduce_sw(int which) {
    unsigned long long acc = 0;
    #pragma unroll
    for (int i = 0; i < 8; i++)
        acc += g_wpart[which][threadIdx.x * 8 + i];
    for (int o = 16; o > 0; o >>= 1)
        acc += __shfl_down_sync(0xFFFFFFFFu, acc, o);
    __shared__ unsigned long long s[8];
    __shared__ float sws;
    if ((threadIdx.x & 31) == 0) s[threadIdx.x >> 5] = acc;
    __syncthreads();
    if (threadIdx.x == 0) {
        unsigned long long t = 0;
        #pragma unroll
        for (int i = 0; i < 8; i++) t += s[i];
        double mean = (double)t * (1.0 / 1099511627776.0) / 67108864.0;
        sws = (float)fmax(mean, (double)EPSF);
    }
    __syncthreads();
    return sws;
}

template <int WHICH>
__global__ void k_quantw(const float4* __restrict__ w) {
    float sw = reduce_sw(WHICH);
    if (blockIdx.x == 0 && threadIdx.x == 0) g_swf[WHICH] = sw;
    char4* q = (char4*)(WHICH ? g_wq2 : g_wq1);
    size_t n4 = WCNT / 4;
    for (size_t i = (size_t)blockIdx.x * blockDim.x + threadIdx.x; i < n4;
         i += (size_t)gridDim.x * blockDim.x) {
        float4 v = w[i];
        char4 o;
        o.x = (signed char)(int)fminf(fmaxf(rintf(__fdiv_rn(v.x, sw)), -1.f), 1.f);
        o.y = (signed char)(int)fminf(fmaxf(rintf(__fdiv_rn(v.y, sw)), -1.f), 1.f);
        o.z = (signed char)(int)fminf(fmaxf(rintf(__fdiv_rn(v.z, sw)), -1.f), 1.f);
        o.w = (signed char)(int)fminf(fmaxf(rintf(__fdiv_rn(v.w, sw)), -1.f), 1.f);
        q[i] = o;
    }
}

static __device__ __forceinline__ signed char q8(float x, float s) {
    return (signed char)(int)fminf(fmaxf(rintf(__fdiv_rn(x, s)), -128.f), 127.f);
}

__global__ void k_quantx(const float* __restrict__ x) {
    int row = blockIdx.x;
    int t = threadIdx.x;
    if (t == 0) g_rowmax[row] = 0u;
    const float4* xr = (const float4*)(x + (size_t)row * HDIM);
    float4 v[4];
    float m = 0.f;
    #pragma unroll
    for (int i = 0; i < 4; i++) {
        v[i] = xr[t * 4 + i];
        m = fmaxf(m, fmaxf(fmaxf(fabsf(v[i].x), fabsf(v[i].y)),
                           fmaxf(fabsf(v[i].z), fabsf(v[i].w))));
    }
    for (int o = 16; o > 0; o >>= 1)
        m = fmaxf(m, __shfl_xor_sync(0xFFFFFFFFu, m, o));
    __shared__ float sm[8];
    __shared__ float ssx;
    if ((t & 31) == 0) sm[t >> 5] = m;
    __syncthreads();
    if (t == 0) {
        float mm = sm[0];
        #pragma unroll
        for (int i = 1; i < 8; i++) mm = fmaxf(mm, sm[i]);
        float sx = __fdiv_rn(fmaxf(mm, EPSF), 127.f);
        g_sx[row] = sx;
        ssx = sx;
    }
    __syncthreads();
    float sx = ssx;
    char4* out = (char4*)(g_xq + (size_t)row * HDIM);
    #pragma unroll
    for (int i = 0; i < 4; i++) {
        float4 u = v[i];
        char4 o;
        o.x = q8(u.x, sx); o.y = q8(u.y, sx); o.z = q8(u.z, sx); o.w = q8(u.w, sx);
        out[t * 4 + i] = o;
    }
}

__global__ void k_quanth() {
    int row = blockIdx.x;
    float sh = __fdiv_rn(fmaxf(__uint_as_float(g_rowmax[row]), EPSF), 127.f);
    if (threadIdx.x == 0) g_sh[row] = sh;
    const float4* hr = (const float4*)(g_h + (size_t)row * IDIM);
    char4* out = (char4*)(g_hq + (size_t)row * IDIM);
    for (int i = threadIdx.x; i < IDIM / 4; i += blockDim.x) {
        float4 u = hr[i];
        char4 o;
        o.x = q8(u.x, sh); o.y = q8(u.y, sh); o.z = q8(u.z, sh); o.w = q8(u.w, sh);
        out[i] = o;
    }
}

// ====== hybrid GEMM, 2 CTAs/SM: 256 threads; warps 0-3 = mma ([0,T)), warps 4-7 = dp4a ([T,NK))
// D[128x64] tile. smem: [0,4S) mma ring (4-stage) | [4S,7S) dp4a ring (3-stage; s32 partials overlay)
// dp4a a-loads use LDS128 (half the a-load instructions; carries 2 words/row across sub-phases).
template <int MODE>
__global__ __launch_bounds__(256, 2) void k_gemm(float* __restrict__ outp) {
    constexpr int K = MODE ? IDIM : HDIM;
    constexpr int N = MODE ? HDIM : IDIM;
    constexpr int NK = K / 64;
    constexpr int T = MODE ? 136 : 34;      // tensor K-chunks (shifted toward dp4a)
    constexpr int ND = NK - T;
    constexpr int ASZ = 128 * 80;           // 10240
    constexpr int STAGE = ASZ + 64 * 80;    // 15360
    const signed char* Ag = MODE ? g_hq : g_xq;
    const signed char* Bg = MODE ? g_wq2 : g_wq1;
    float* Out = MODE ? outp : g_h;
    const float* srow = MODE ? g_sh : g_sx;

    extern __shared__ __align__(128) char smem[];
    uint32_t smbase = smem_u32(smem);
    int* Ssm = (int*)(smem + 4 * STAGE);    // overlays dp4a ring after its loop; 128 x 68 s32

    int tid = threadIdx.x;
    int gt = tid & 127;
    bool is_mma = tid < 128;

    int mt = MODE ? blockIdx.y : blockIdx.x;
    int nt = MODE ? blockIdx.x : blockIdx.y;
    int mb = mt * 128, nb = nt * 64;

    uint32_t gbase = smbase + (is_mma ? 0u : (uint32_t)(4 * STAGE));
    auto load_stage = [&](int s, int kc) {
        uint32_t base = gbase + s * STAGE;
        const signed char* ag = Ag + (size_t)mb * K + (size_t)kc * 64;
        const signed char* bg = Bg + (size_t)nb * K + (size_t)kc * 64;
        #pragma unroll
        for (int i = 0; i < 4; i++) {       // A: 128 rows x 4 chunks of 16B
            int c = gt + i * 128;
            int r = c >> 2, cc = c & 3;
            int cc2 = is_mma ? cc : ((cc + (r >> 3)) & 3);   // dp4a in-row rotation
            CP_ASYNC16(base + r * 80 + cc2 * 16, ag + (size_t)r * K + cc * 16);
        }
        #pragma unroll
        for (int i = 0; i < 2; i++) {       // B: 64 rows x 4 chunks
            int c = gt + i * 128;
            int r = c >> 2, cc = c & 3;
            CP_ASYNC16(base + ASZ + r * 80 + cc * 16, bg + (size_t)r * K + cc * 16);
        }
        CP_COMMIT();
    };

    int acc[4][4][4];  // mma accumulators (mma group only)

    if (is_mma) {
        // ---------------- tensor group: 4 warps, 64x32 warp tiles, 4-stage pipelined ----
        int wid = gt >> 5, lane = gt & 31;
        int wm = wid & 1, wn = wid >> 1;    // 2 x 2 warp grid
        int rq = lane & 7, q = lane >> 3;
        #pragma unroll
        for (int i = 0; i < 4; i++)
            #pragma unroll
            for (int j = 0; j < 4; j++)
                #pragma unroll
                for (int c = 0; c < 4; c++) acc[i][j][c] = 0;

        int lrow = rq + (q & 1) * 8;
        int lcol = (q >> 1) * 16;
        int aoff[4], boff[2];
        #pragma unroll
        for (int m = 0; m < 4; m++) aoff[m] = (wm * 64 + m * 16 + lrow) * 80 + lcol;
        #pragma unroll
        for (int bt = 0; bt < 2; bt++) boff[bt] = ASZ + (wn * 32 + bt * 16 + lrow) * 80 + lcol;

        load_stage(0, 0);
        load_stage(1, 1);
        load_stage(2, 2);
        CP_WAIT(2);                         // own stage-0 writes done
        BARRIER(1);                         // everyone's stage-0 writes visible

        uint32_t af0[4][4], bf0[2][4], af1[4][4], bf1[2][4];
        #pragma unroll
        for (int m = 0; m < 4; m++)
            LDSM4(af0[m][0], af0[m][1], af0[m][2], af0[m][3], gbase + aoff[m]);
        #pragma unroll
        for (int bt = 0; bt < 2; bt++)
            LDSM4(bf0[bt][0], bf0[bt][1], bf0[bt][2], bf0[bt][3], gbase + boff[bt]);

        for (int k = 0; k < T; k++) {
            uint32_t sA = gbase + (k & 3) * STAGE;
            #pragma unroll
            for (int m = 0; m < 4; m++)
                LDSM4(af1[m][0], af1[m][1], af1[m][2], af1[m][3], sA + aoff[m] + 32);
            #pragma unroll
            for (int bt = 0; bt < 2; bt++)
                LDSM4(bf1[bt][0], bf1[bt][1], bf1[bt][2], bf1[bt][3], sA + boff[bt] + 32);
            #pragma unroll
            for (int m = 0; m < 4; m++)
                #pragma unroll
                for (int bt = 0; bt < 2; bt++) {
                    MMA_S8(acc[m][bt * 2 + 0], af0[m], bf0[bt][0], bf0[bt][2]);
                    MMA_S8(acc[m][bt * 2 + 1], af0[m], bf0[bt][1], bf0[bt][3]);
                }
            if (k + 3 < T)      { load_stage((k + 3) & 3, k + 3); CP_WAIT(2); }
            else if (k + 2 < T) { CP_WAIT(1); }
            else if (k + 1 < T) { CP_WAIT(0); }
            if (k + 1 < T) {
                BARRIER(1);
                uint32_t sN = gbase + ((k + 1) & 3) * STAGE;
                #pragma unroll
                for (int m = 0; m < 4; m++)
                    LDSM4(af0[m][0], af0[m][1], af0[m][2], af0[m][3], sN + aoff[m]);
                #pragma unroll
                for (int bt = 0; bt < 2; bt++)
                    LDSM4(bf0[bt][0], bf0[bt][1], bf0[bt][2], bf0[bt][3], sN + boff[bt]);
            }
            #pragma unroll
            for (int m = 0; m < 4; m++)
                #pragma unroll
                for (int bt = 0; bt < 2; bt++) {
                    MMA_S8(acc[m][bt * 2 + 0], af1[m], bf1[bt][0], bf1[bt][2]);
                    MMA_S8(acc[m][bt * 2 + 1], af1[m], bf1[bt][1], bf1[bt][3]);
                }
        }
    } else {
        // ---------------- dp4a group: 4 warps, 8x8 outputs/thread, 3-stage ----------------
        int r8 = (gt >> 3) * 8;             // 16 row-blocks of 8
        int c0 = gt & 7;                    // cols = c0 + 8*j2
        int rot = (r8 >> 3) & 3;            // chunk rotation for this thread's rows
        int dacc[8][8];
        #pragma unroll
        for (int i = 0; i < 8; i++)
            #pragma unroll
            for (int j = 0; j < 8; j++) dacc[i][j] = 0;

        load_stage(0, T);
        load_stage(1, T + 1);
        for (int k = 0; k < ND; k++) {
            if (k < ND - 1) { CP_WAIT(1); } else { CP_WAIT(0); }
            BARRIER(2);
            if (k + 2 < ND) load_stage((k + 2) % 3, T + k + 2);

            uint32_t sA = gbase + (k % 3) * STAGE;
            uint32_t sB = sA + ASZ;
            #pragma unroll
            for (int cp2 = 0; cp2 < 4; cp2++) {
                // a: one LDS128 per row covers sub-phases 2*cp2 and 2*cp2+1
                int aoffc = ((cp2 + rot) & 3) * 16;      // rotated 16B chunk addr
                uint32_t a2[8], a3[8];
                uint32_t b0[8], b1[8];
                // sub-phase A (cp = 2*cp2): b words 4*cp2, 4*cp2+1
                #pragma unroll
                for (int j2 = 0; j2 < 8; j2++)
                    LDS64(b0[j2], b1[j2], sB + (c0 + 8 * j2) * 80 + cp2 * 16);
                #pragma unroll
                for (int i = 0; i < 8; i++) {
                    uint32_t w0, w1, w2, w3;
                    LDS128(w0, w1, w2, w3, sA + (r8 + i) * 80 + aoffc);
                    a2[i] = w2; a3[i] = w3;
                    #pragma unroll
                    for (int j2 = 0; j2 < 8; j2++) {
                        dacc[i][j2] = __dp4a((int)w0, (int)b0[j2], dacc[i][j2]);
                        dacc[i][j2] = __dp4a((int)w1, (int)b1[j2], dacc[i][j2]);
                    }
                }
                // sub-phase B (cp = 2*cp2+1): b words 4*cp2+2, 4*cp2+3
                #pragma unroll
                for (int j2 = 0; j2 < 8; j2++)
                    LDS64(b0[j2], b1[j2], sB + (c0 + 8 * j2) * 80 + cp2 * 16 + 8);
                #pragma unroll
                for (int i = 0; i < 8; i++) {
                    #pragma unroll
                    for (int j2 = 0; j2 < 8; j2++) {
                        dacc[i][j2] = __dp4a((int)a2[i], (int)b0[j2], dacc[i][j2]);
                        dacc[i][j2] = __dp4a((int)a3[i], (int)b1[j2], dacc[i][j2]);
                    }
                }
            }
        }
        BARRIER(2);   // all dp4a warps done reading ring before overlaying with partials
        #pragma unroll
        for (int i = 0; i < 8; i++)
            #pragma unroll
            for (int j2 = 0; j2 < 8; j2++)
                Ssm[(r8 + i) * 68 + c0 + 8 * j2] = dacc[i][j2];
    }

    __syncthreads();   // join: dp4a partials visible

    if (is_mma) {
        // ---------------- epilogue: combine + dequant (+gelu/rowmax) ----------------
        int wid = gt >> 5, lane = gt & 31;
        int wm = wid & 1, wn = wid >> 1;
        int g = lane >> 2, tig = lane & 3;
        float sw = g_swf[MODE];
        #pragma unroll
        for (int m = 0; m < 4; m++) {
            int rL0 = wm * 64 + m * 16 + g;
            int row0 = mb + rL0;
            int row1 = row0 + 8;
            float s0 = srow[row0] * sw;
            float s1 = srow[row1] * sw;
            float mx0 = 0.f, mx1 = 0.f;
            #pragma unroll
            for (int j = 0; j < 4; j++) {
                int colL = wn * 32 + j * 8 + tig * 2;
                int2 d0 = *(const int2*)(Ssm + rL0 * 68 + colL);
                int2 d1 = *(const int2*)(Ssm + (rL0 + 8) * 68 + colL);
                float v00 = (float)(acc[m][j][0] + d0.x) * s0;
                float v01 = (float)(acc[m][j][1] + d0.y) * s0;
                float v10 = (float)(acc[m][j][2] + d1.x) * s1;
                float v11 = (float)(acc[m][j][3] + d1.y) * s1;
                if (MODE == 0) {
                    v00 = 0.5f * v00 * (1.f + erff(v00 * 0.70710678118654752f));
                    v01 = 0.5f * v01 * (1.f + erff(v01 * 0.70710678118654752f));
                    v10 = 0.5f * v10 * (1.f + erff(v10 * 0.70710678118654752f));
                    v11 = 0.5f * v11 * (1.f + erff(v11 * 0.70710678118654752f));
                    mx0 = fmaxf(mx0, fmaxf(fabsf(v00), fabsf(v01)));
                    mx1 = fmaxf(mx1, fmaxf(fabsf(v10), fabsf(v11)));
                }
                *(float2*)(Out + (size_t)row0 * N + nb + colL) = make_float2(v00, v01);
                *(float2*)(Out + (size_t)row1 * N + nb + colL) = make_float2(v10, v11);
            }
            if (MODE == 0) {
                #pragma unroll
                for (int o = 1; o < 4; o <<= 1) {
                    mx0 = fmaxf(mx0, __shfl_xor_sync(0xFFFFFFFFu, mx0, o));
                    mx1 = fmaxf(mx1, __shfl_xor_sync(0xFFFFFFFFu, mx1, o));
                }
                if (tig == 0) {
                    atomicMax(&g_rowmax[row0], __float_as_uint(mx0));
                    atomicMax(&g_rowmax[row1], __float_as_uint(mx1));
                }
            }
        }
    }
}

// ---------------- launch ----------------
extern "C" void kernel_launch(void* const* d_in, const int* in_sizes, int n_in,
                              void* d_out, int out_size) {
    const float* x  = (const float*)d_in[0];
    const float* W1 = (const float*)d_in[1];
    const float* W2 = (const float*)d_in[2];
    float* out = (float*)d_out;

    const int SMEM = 7 * 15360;   // 107520; 2 CTAs/SM
    cudaFuncSetAttribute(k_gemm<0>, cudaFuncAttributeMaxDynamicSharedMemorySize, SMEM);
    cudaFuncSetAttribute(k_gemm<1>, cudaFuncAttributeMaxDynamicSharedMemorySize, SMEM);

    k_abssum<<<2048, 256>>>((const float4*)W1, 0);   // 0
    k_quantw<0><<<4096, 256>>>((const float4*)W1);   // 1
    k_quantx<<<MTOT, 256>>>(x);                      // 2 (also zeroes rowmax)
    k_gemm<0><<<dim3(64, 256), 256, SMEM>>>(out);    // 3  <- ncu capture slot
    k_quanth<<<MTOT, 256>>>();                       // 4
    k_abssum<<<2048, 256>>>((const float4*)W2, 1);   // 5
    k_quantw<1><<<4096, 256>>>((const float4*)W2);   // 6
    k_gemm<1><<<dim3(64, 64), 256, SMEM>>>(out);     // 7
}

// round 14
// speedup vs baseline: 1.7829x; 1.0052x over previous
#include <cuda_runtime.h>
#include <cuda_bf16.h>
#include <cstdint>
#include <cstddef>

#define MTOT 8192
#define HDIM 4096
#define IDIM 16384
#define WCNT 67108864ULL
#define EPSF 1e-5f

// ---------------- scratch (device globals; no allocations) ----------------
__device__ __align__(16) signed char g_wq1[(size_t)IDIM * HDIM];  // 64MB
__device__ __align__(16) signed char g_wq2[(size_t)IDIM * HDIM];  // 64MB
__device__ __align__(16) signed char g_xq[(size_t)MTOT * HDIM];   // 32MB
__device__ __align__(16) signed char g_hq[(size_t)MTOT * IDIM];   // 128MB
__device__ __align__(16) float g_h[(size_t)MTOT * IDIM];          // 512MB
__device__ float g_sx[MTOT];
__device__ float g_sh[MTOT];
__device__ unsigned int g_rowmax[MTOT];
__device__ unsigned long long g_wpart[2][2048];
__device__ float g_swf[2];

// ---------------- PTX helpers ----------------
static __device__ __forceinline__ uint32_t smem_u32(const void* p) {
    uint32_t a;
    asm("{ .reg .u64 t; cvta.to.shared.u64 t, %1; cvt.u32.u64 %0, t; }" : "=r"(a) : "l"(p));
    return a;
}
#define CP_ASYNC16(dst, src) \
    asm volatile("cp.async.cg.shared.global [%0], [%1], 16;" :: "r"(dst), "l"(src))
#define CP_COMMIT() asm volatile("cp.async.commit_group;" ::: "memory")
#define CP_WAIT(n)  asm volatile("cp.async.wait_group " #n ";" ::: "memory")
#define BARRIER(id) asm volatile("bar.sync %0, 128;" :: "r"(id) : "memory")

#define LDSM4(r0, r1, r2, r3, addr) \
    asm volatile("ldmatrix.sync.aligned.m8n8.x4.shared.b16 {%0,%1,%2,%3}, [%4];" \
                 : "=r"(r0), "=r"(r1), "=r"(r2), "=r"(r3) : "r"(addr))

#define MMA_S8(d, a, b0, b1) \
    asm volatile("mma.sync.aligned.m16n8k32.row.col.s32.s8.s8.s32 " \
                 "{%0,%1,%2,%3}, {%4,%5,%6,%7}, {%8,%9}, {%0,%1,%2,%3};" \
                 : "+r"((d)[0]), "+r"((d)[1]), "+r"((d)[2]), "+r"((d)[3]) \
                 : "r"((a)[0]), "r"((a)[1]), "r"((a)[2]), "r"((a)[3]), \
                   "r"(b0), "r"(b1))

#define LDS64(r0, r1, addr) \
    asm volatile("ld.shared.v2.u32 {%0,%1},[%2];" : "=r"(r0), "=r"(r1) : "r"(addr))
#define LDS128(r0, r1, r2, r3, addr) \
    asm volatile("ld.shared.v4.u32 {%0,%1,%2,%3},[%4];" \
                 : "=r"(r0), "=r"(r1), "=r"(r2), "=r"(r3) : "r"(addr))

// ---------------- elementwise kernels ----------------
__global__ void k_abssum(const float4* __restrict__ w, int which) {
    unsigned long long a0 = 0, a1 = 0, a2 = 0, a3 = 0;   // 4-way ILP
    size_t n4 = WCNT / 4;
    for (size_t i = (size_t)blockIdx.x * blockDim.x + threadIdx.x; i < n4;
         i += (size_t)gridDim.x * blockDim.x) {
        float4 v = w[i];
        a0 += (unsigned long long)llrintf(fabsf(v.x) * 1099511627776.f);
        a1 += (unsigned long long)llrintf(fabsf(v.y) * 1099511627776.f);
        a2 += (unsigned long long)llrintf(fabsf(v.z) * 1099511627776.f);
        a3 += (unsigned long long)llrintf(fabsf(v.w) * 1099511627776.f);
    }
    unsigned long long acc = (a0 + a1) + (a2 + a3);
    for (int o = 16; o > 0; o >>= 1)
        acc += __shfl_down_sync(0xFFFFFFFFu, acc, o);
    __shared__ unsigned long long s[8];
    if ((threadIdx.x & 31) == 0) s[threadIdx.x >> 5] = acc;
    __syncthreads();
    if (threadIdx.x == 0) {
        unsigned long long t = 0;
        #pragma unroll
        for (int i = 0; i < 8; i++) t += s[i];
        g_wpart[which][blockIdx.x] = t;
    }
}

static __device__ __forceinline__ float reduce_sw(int which) {
    unsigned long long acc = 0;
    #pragma unroll
    for (int i = 0; i < 8; i++)
        acc += g_wpart[which][threadIdx.x * 8 + i];
    for (int o = 16; o > 0; o >>= 1)
        acc += __shfl_down_sync(0xFFFFFFFFu, acc, o);
    __shared__ unsigned long long s[8];
    __shared__ float sws;
    if ((threadIdx.x & 31) == 0) s[threadIdx.x >> 5] = acc;
    __syncthreads();
    if (threadIdx.x == 0) {
        unsigned long long t = 0;
        #pragma unroll
        for (int i = 0; i < 8; i++) t += s[i];
        double mean = (double)t * (1.0 / 1099511627776.0) / 67108864.0;
        sws = (float)fmax(mean, (double)EPSF);
    }
    __syncthreads();
    return sws;
}

template <int WHICH>
__global__ void k_quantw(const float4* __restrict__ w) {
    float sw = reduce_sw(WHICH);
    if (blockIdx.x == 0 && threadIdx.x == 0) g_swf[WHICH] = sw;
    char4* q = (char4*)(WHICH ? g_wq2 : g_wq1);
    size_t n4 = WCNT / 4;
    for (size_t i = (size_t)blockIdx.x * blockDim.x + threadIdx.x; i < n4;
         i += (size_t)gridDim.x * blockDim.x) {
        float4 v = w[i];
        char4 o;
        o.x = (signed char)(int)fminf(fmaxf(rintf(__fdiv_rn(v.x, sw)), -1.f), 1.f);
        o.y = (signed char)(int)fminf(fmaxf(rintf(__fdiv_rn(v.y, sw)), -1.f), 1.f);
        o.z = (signed char)(int)fminf(fmaxf(rintf(__fdiv_rn(v.z, sw)), -1.f), 1.f);
        o.w = (signed char)(int)fminf(fmaxf(rintf(__fdiv_rn(v.w, sw)), -1.f), 1.f);
        q[i] = o;
    }
}

static __device__ __forceinline__ signed char q8(float x, float s) {
    return (signed char)(int)fminf(fmaxf(rintf(__fdiv_rn(x, s)), -128.f), 127.f);
}

__global__ void k_quantx(const float* __restrict__ x) {
    int row = blockIdx.x;
    int t = threadIdx.x;
    if (t == 0) g_rowmax[row] = 0u;
    const float4* xr = (const float4*)(x + (size_t)row * HDIM);
    float4 v[4];
    float m = 0.f;
    #pragma unroll
    for (int i = 0; i < 4; i++) {
        v[i] = xr[t * 4 + i];
        m = fmaxf(m, fmaxf(fmaxf(fabsf(v[i].x), fabsf(v[i].y)),
                           fmaxf(fabsf(v[i].z), fabsf(v[i].w))));
    }
    for (int o = 16; o > 0; o >>= 1)
        m = fmaxf(m, __shfl_xor_sync(0xFFFFFFFFu, m, o));
    __shared__ float sm[8];
    __shared__ float ssx;
    if ((t & 31) == 0) sm[t >> 5] = m;
    __syncthreads();
    if (t == 0) {
        float mm = sm[0];
        #pragma unroll
        for (int i = 1; i < 8; i++) mm = fmaxf(mm, sm[i]);
        float sx = __fdiv_rn(fmaxf(mm, EPSF), 127.f);
        g_sx[row] = sx;
        ssx = sx;
    }
    __syncthreads();
    float sx = ssx;
    char4* out = (char4*)(g_xq + (size_t)row * HDIM);
    #pragma unroll
    for (int i = 0; i < 4; i++) {
        float4 u = v[i];
        char4 o;
        o.x = q8(u.x, sx); o.y = q8(u.y, sx); o.z = q8(u.z, sx); o.w = q8(u.w, sx);
        out[t * 4 + i] = o;
    }
}

__global__ void k_quanth() {
    int row = blockIdx.x;
    float sh = __fdiv_rn(fmaxf(__uint_as_float(g_rowmax[row]), EPSF), 127.f);
    if (threadIdx.x == 0) g_sh[row] = sh;
    const float4* hr = (const float4*)(g_h + (size_t)row * IDIM);
    char4* out = (char4*)(g_hq + (size_t)row * IDIM);
    for (int i = threadIdx.x; i < IDIM / 4; i += blockDim.x) {
        float4 u = hr[i];
        char4 o;
        o.x = q8(u.x, sh); o.y = q8(u.y, sh); o.z = q8(u.z, sh); o.w = q8(u.w, sh);
        out[i] = o;
    }
}

// ====== hybrid GEMM, 2 CTAs/SM: 256 threads.
// ROLE SWAP vs R12: warps 4-7 (HIGH arbiter priority) = mma, warps 0-3 = dp4a.
// B300 SMSP arbiter is highest-wid-first; mma warps' sparse LDSM/MMA issues must
// preempt the dense dp4a stream to keep the tensor pipe fed.
// D[128x64] tile. smem: [0,4S) mma ring (4-stage) | [4S,7S) dp4a ring (3-stage; s32 partials overlay)
template <int MODE>
__global__ __launch_bounds__(256, 2) void k_gemm(float* __restrict__ outp) {
    constexpr int K = MODE ? IDIM : HDIM;
    constexpr int N = MODE ? HDIM : IDIM;
    constexpr int NK = K / 64;
    constexpr int T = MODE ? 136 : 34;      // tensor K-chunks
    constexpr int ND = NK - T;
    constexpr int ASZ = 128 * 80;           // 10240
    constexpr int STAGE = ASZ + 64 * 80;    // 15360
    const signed char* Ag = MODE ? g_hq : g_xq;
    const signed char* Bg = MODE ? g_wq2 : g_wq1;
    float* Out = MODE ? outp : g_h;
    const float* srow = MODE ? g_sh : g_sx;

    extern __shared__ __align__(128) char smem[];
    uint32_t smbase = smem_u32(smem);
    int* Ssm = (int*)(smem + 4 * STAGE);    // overlays dp4a ring after its loop; 128 x 68 s32

    int tid = threadIdx.x;
    int gt = tid & 127;
    bool is_mma = tid >= 128;               // mma group = warps 4-7 (hi-wid priority)

    int mt = MODE ? blockIdx.y : blockIdx.x;
    int nt = MODE ? blockIdx.x : blockIdx.y;
    int mb = mt * 128, nb = nt * 64;

    uint32_t gbase = smbase + (is_mma ? 0u : (uint32_t)(4 * STAGE));
    auto load_stage = [&](int s, int kc) {
        uint32_t base = gbase + s * STAGE;
        const signed char* ag = Ag + (size_t)mb * K + (size_t)kc * 64;
        const signed char* bg = Bg + (size_t)nb * K + (size_t)kc * 64;
        #pragma unroll
        for (int i = 0; i < 4; i++) {       // A: 128 rows x 4 chunks of 16B
            int c = gt + i * 128;
            int r = c >> 2, cc = c & 3;
            int cc2 = is_mma ? cc : ((cc + (r >> 3)) & 3);   // dp4a in-row rotation
            CP_ASYNC16(base + r * 80 + cc2 * 16, ag + (size_t)r * K + cc * 16);
        }
        #pragma unroll
        for (int i = 0; i < 2; i++) {       // B: 64 rows x 4 chunks
            int c = gt + i * 128;
            int r = c >> 2, cc = c & 3;
            CP_ASYNC16(base + ASZ + r * 80 + cc * 16, bg + (size_t)r * K + cc * 16);
        }
        CP_COMMIT();
    };

    int acc[4][4][4];  // mma accumulators (mma group only)

    if (is_mma) {
        // ---------------- tensor group: 4 warps, 64x32 warp tiles, 4-stage pipelined ----
        int wid = gt >> 5, lane = gt & 31;
        int wm = wid & 1, wn = wid >> 1;    // 2 x 2 warp grid
        int rq = lane & 7, q = lane >> 3;
        #pragma unroll
        for (int i = 0; i < 4; i++)
            #pragma unroll
            for (int j = 0; j < 4; j++)
                #pragma unroll
                for (int c = 0; c < 4; c++) acc[i][j][c] = 0;

        int lrow = rq + (q & 1) * 8;
        int lcol = (q >> 1) * 16;
        int aoff[4], boff[2];
        #pragma unroll
        for (int m = 0; m < 4; m++) aoff[m] = (wm * 64 + m * 16 + lrow) * 80 + lcol;
        #pragma unroll
        for (int bt = 0; bt < 2; bt++) boff[bt] = ASZ + (wn * 32 + bt * 16 + lrow) * 80 + lcol;

        load_stage(0, 0);
        load_stage(1, 1);
        load_stage(2, 2);
        CP_WAIT(2);                         // own stage-0 writes done
        BARRIER(1);                         // everyone's stage-0 writes visible

        uint32_t af0[4][4], bf0[2][4], af1[4][4], bf1[2][4];
        #pragma unroll
        for (int m = 0; m < 4; m++)
            LDSM4(af0[m][0], af0[m][1], af0[m][2], af0[m][3], gbase + aoff[m]);
        #pragma unroll
        for (int bt = 0; bt < 2; bt++)
            LDSM4(bf0[bt][0], bf0[bt][1], bf0[bt][2], bf0[bt][3], gbase + boff[bt]);

        for (int k = 0; k < T; k++) {
            uint32_t sA = gbase + (k & 3) * STAGE;
            #pragma unroll
            for (int m = 0; m < 4; m++)
                LDSM4(af1[m][0], af1[m][1], af1[m][2], af1[m][3], sA + aoff[m] + 32);
            #pragma unroll
            for (int bt = 0; bt < 2; bt++)
                LDSM4(bf1[bt][0], bf1[bt][1], bf1[bt][2], bf1[bt][3], sA + boff[bt] + 32);
            #pragma unroll
            for (int m = 0; m < 4; m++)
                #pragma unroll
                for (int bt = 0; bt < 2; bt++) {
                    MMA_S8(acc[m][bt * 2 + 0], af0[m], bf0[bt][0], bf0[bt][2]);
                    MMA_S8(acc[m][bt * 2 + 1], af0[m], bf0[bt][1], bf0[bt][3]);
                }
            if (k + 3 < T)      { load_stage((k + 3) & 3, k + 3); CP_WAIT(2); }
            else if (k + 2 < T) { CP_WAIT(1); }
            else if (k + 1 < T) { CP_WAIT(0); }
            if (k + 1 < T) {
                BARRIER(1);
                uint32_t sN = gbase + ((k + 1) & 3) * STAGE;
                #pragma unroll
                for (int m = 0; m < 4; m++)
                    LDSM4(af0[m][0], af0[m][1], af0[m][2], af0[m][3], sN + aoff[m]);
                #pragma unroll
                for (int bt = 0; bt < 2; bt++)
                    LDSM4(bf0[bt][0], bf0[bt][1], bf0[bt][2], bf0[bt][3], sN + boff[bt]);
            }
            #pragma unroll
            for (int m = 0; m < 4; m++)
                #pragma unroll
                for (int bt = 0; bt < 2; bt++) {
                    MMA_S8(acc[m][bt * 2 + 0], af1[m], bf1[bt][0], bf1[bt][2]);
                    MMA_S8(acc[m][bt * 2 + 1], af1[m], bf1[bt][1], bf1[bt][3]);
                }
        }
    } else {
        // ---------------- dp4a group: 4 warps (wid 0-3), 8x8 outputs/thread, 3-stage ----
        int r8 = (gt >> 3) * 8;             // 16 row-blocks of 8
        int c0 = gt & 7;                    // cols = c0 + 8*j2
        int rot = (r8 >> 3) & 3;            // chunk rotation for this thread's rows
        int dacc[8][8];
        #pragma unroll
        for (int i = 0; i < 8; i++)
            #pragma unroll
            for (int j = 0; j < 8; j++) dacc[i][j] = 0;

        load_stage(0, T);
        load_stage(1, T + 1);
        for (int k = 0; k < ND; k++) {
            if (k < ND - 1) { CP_WAIT(1); } else { CP_WAIT(0); }
            BARRIER(2);
            if (k + 2 < ND) load_stage((k + 2) % 3, T + k + 2);

            uint32_t sA = gbase + (k % 3) * STAGE;
            uint32_t sB = sA + ASZ;
            #pragma unroll
            for (int cp2 = 0; cp2 < 4; cp2++) {
                int aoffc = ((cp2 + rot) & 3) * 16;      // rotated 16B chunk addr
                uint32_t a2[8], a3[8];
                uint32_t b0[8], b1[8];
                #pragma unroll
                for (int j2 = 0; j2 < 8; j2++)
                    LDS64(b0[j2], b1[j2], sB + (c0 + 8 * j2) * 80 + cp2 * 16);
                #pragma unroll
                for (int i = 0; i < 8; i++) {
                    uint32_t w0, w1, w2, w3;
                    LDS128(w0, w1, w2, w3, sA + (r8 + i) * 80 + aoffc);
                    a2[i] = w2; a3[i] = w3;
                    #pragma unroll
                    for (int j2 = 0; j2 < 8; j2++) {
                        dacc[i][j2] = __dp4a((int)w0, (int)b0[j2], dacc[i][j2]);
                        dacc[i][j2] = __dp4a((int)w1, (int)b1[j2], dacc[i][j2]);
                    }
                }
                #pragma unroll
                for (int j2 = 0; j2 < 8; j2++)
                    LDS64(b0[j2], b1[j2], sB + (c0 + 8 * j2) * 80 + cp2 * 16 + 8);
                #pragma unroll
                for (int i = 0; i < 8; i++) {
                    #pragma unroll
                    for (int j2 = 0; j2 < 8; j2++) {
                        dacc[i][j2] = __dp4a((int)a2[i], (int)b0[j2], dacc[i][j2]);
                        dacc[i][j2] = __dp4a((int)a3[i], (int)b1[j2], dacc[i][j2]);
                    }
                }
            }
        }
        BARRIER(2);   // all dp4a warps done reading ring before overlaying with partials
        #pragma unroll
        for (int i = 0; i < 8; i++)
            #pragma unroll
            for (int j2 = 0; j2 < 8; j2++)
                Ssm[(r8 + i) * 68 + c0 + 8 * j2] = dacc[i][j2];
    }

    __syncthreads();   // join: dp4a partials visible

    if (is_mma) {
        // ---------------- epilogue: combine + dequant (+gelu/rowmax) ----------------
        int wid = gt >> 5, lane = gt & 31;
        int wm = wid & 1, wn = wid >> 1;
        int g = lane >> 2, tig = lane & 3;
        float sw = g_swf[MODE];
        #pragma unroll
        for (int m = 0; m < 4; m++) {
            int rL0 = wm * 64 + m * 16 + g;
            int row0 = mb + rL0;
            int row1 = row0 + 8;
            float s0 = srow[row0] * sw;
            float s1 = srow[row1] * sw;
            float mx0 = 0.f, mx1 = 0.f;
            #pragma unroll
            for (int j = 0; j < 4; j++) {
                int colL = wn * 32 + j * 8 + tig * 2;
                int2 d0 = *(const int2*)(Ssm + rL0 * 68 + colL);
                int2 d1 = *(const int2*)(Ssm + (rL0 + 8) * 68 + colL);
                float v00 = (float)(acc[m][j][0] + d0.x) * s0;
                float v01 = (float)(acc[m][j][1] + d0.y) * s0;
                float v10 = (float)(acc[m][j][2] + d1.x) * s1;
                float v11 = (float)(acc[m][j][3] + d1.y) * s1;
                if (MODE == 0) {
                    v00 = 0.5f * v00 * (1.f + erff(v00 * 0.70710678118654752f));
                    v01 = 0.5f * v01 * (1.f + erff(v01 * 0.70710678118654752f));
                    v10 = 0.5f * v10 * (1.f + erff(v10 * 0.70710678118654752f));
                    v11 = 0.5f * v11 * (1.f + erff(v11 * 0.70710678118654752f));
                    mx0 = fmaxf(mx0, fmaxf(fabsf(v00), fabsf(v01)));
                    mx1 = fmaxf(mx1, fmaxf(fabsf(v10), fabsf(v11)));
                }
                *(float2*)(Out + (size_t)row0 * N + nb + colL) = make_float2(v00, v01);
                *(float2*)(Out + (size_t)row1 * N + nb + colL) = make_float2(v10, v11);
            }
            if (MODE == 0) {
                #pragma unroll
                for (int o = 1; o < 4; o <<= 1) {
                    mx0 = fmaxf(mx0, __shfl_xor_sync(0xFFFFFFFFu, mx0, o));
                    mx1 = fmaxf(mx1, __shfl_xor_sync(0xFFFFFFFFu, mx1, o));
                }
                if (tig == 0) {
                    atomicMax(&g_rowmax[row0], __float_as_uint(mx0));
                    atomicMax(&g_rowmax[row1], __float_as_uint(mx1));
                }
            }
        }
    }
}

// ---------------- launch ----------------
extern "C" void kernel_launch(void* const* d_in, const int* in_sizes, int n_in,
                              void* d_out, int out_size) {
    const float* x  = (const float*)d_in[0];
    const float* W1 = (const float*)d_in[1];
    const float* W2 = (const float*)d_in[2];
    float* out = (float*)d_out;

    const int SMEM = 7 * 15360;   // 107520; 2 CTAs/SM
    cudaFuncSetAttribute(k_gemm<0>, cudaFuncAttributeMaxDynamicSharedMemorySize, SMEM);
    cudaFuncSetAttribute(k_gemm<1>, cudaFuncAttributeMaxDynamicSharedMemorySize, SMEM);

    k_abssum<<<2048, 256>>>((const float4*)W1, 0);   // 0
    k_quantw<0><<<4096, 256>>>((const float4*)W1);   // 1
    k_quantx<<<MTOT, 256>>>(x);                      // 2 (also zeroes rowmax)
    k_gemm<0><<<dim3(64, 256), 256, SMEM>>>(out);    // 3  <- ncu capture slot
    k_quanth<<<MTOT, 256>>>();                       // 4
    k_abssum<<<2048, 256>>>((const float4*)W2, 1);   // 5
    k_quantw<1><<<4096, 256>>>((const float4*)W2);   // 6
    k_gemm<1><<<dim3(64, 64), 256, SMEM>>>(out);     // 7
}